// round 8
// baseline (speedup 1.0000x reference)
#include <cuda_runtime.h>

#define NN 50000
#define EE 800000

// ---------------- scratch layout (floats) ----------------
constexpr size_t OFF_P     = 0;                              // N*384: [x_l | A | B]; later reused as z1 (N*256)
constexpr size_t OFF_HMOD  = OFF_P     + (size_t)NN * 384;   // N*128: h_mod; later reused as LN output
constexpr size_t OFF_LOGIT = OFF_HMOD  + (size_t)NN * 128;   // E*4: logits, overwritten in-place with exp
constexpr size_t OFF_AMAX  = OFF_LOGIT + (size_t)EE * 4;     // N*4
constexpr size_t OFF_DENOM = OFF_AMAX  + (size_t)NN * 4;     // N*4
constexpr size_t OFF_AGGR  = OFF_DENOM + (size_t)NN * 4;     // N*128 (GAT out, atomically accumulated)
constexpr size_t OFF_AGGR2 = OFF_AGGR  + (size_t)NN * 128;   // N*128 (after Wp)
constexpr size_t OFF_STYLE = OFF_AGGR2 + (size_t)NN * 128;   // 256 (gamma|beta)
constexpr size_t OFF_BIAS2 = OFF_STYLE + 256;                // 128 (gat_b@Wp + bp)
constexpr size_t OFF_ZERO  = OFF_BIAS2 + 128;                // 128 zeros (never written)
constexpr size_t SCRATCH_TOTAL = OFF_ZERO + 128;

__device__ __align__(16) float g_scratch[SCRATCH_TOTAL];
__device__ int g_is64;   // 1 if edge_index buffer is int64, 0 if int32

// ---------------- helpers ----------------
__device__ __forceinline__ float geluf(float x) {
    return 0.5f * x * (1.f + erff(x * 0.70710678118654752440f));
}

__device__ __forceinline__ void atomicMaxF(float* addr, float v) {
    if (v >= 0.f) atomicMax((int*)addr, __float_as_int(v));
    else          atomicMin((unsigned int*)addr, __float_as_uint(v));
}

// decode edge index element `pos` (element space), clamped to [0, M)
__device__ __forceinline__ int eidx(const int* __restrict__ ei32, size_t pos, int is64, int M) {
    int v = ei32[is64 ? (pos << 1) : pos];
    if ((unsigned)v >= (unsigned)M) v = 0;
    return v;
}

// ---------------- detect edge_index dtype ----------------
__global__ void k_detect(const int* __restrict__ ei32) {
    int z = 0;
#pragma unroll
    for (int i = 0; i < 16; i++) z |= ei32[2 * i + 1];
    g_is64 = (z == 0) ? 1 : 0;
}

// ---------------- tiny precompute: style = t_emb@fc_W+fc_b ; bias2 = gat_b@Wp+bp ----------------
__global__ void k_style(const float* __restrict__ t_emb, const float* __restrict__ fcW,
                        const float* __restrict__ fcb, const float* __restrict__ gatb,
                        const float* __restrict__ Wp, const float* __restrict__ bp) {
    int j = threadIdx.x;
    if (j < 256) {
        float s = fcb[j];
        for (int i = 0; i < 128; i++) s += t_emb[i] * fcW[i * 256 + j];
        g_scratch[OFF_STYLE + j] = s;
    } else if (j < 384) {
        int c = j - 256;
        float s = bp[c];
        for (int i = 0; i < 128; i++) s += gatb[i] * Wp[i * 128 + c];
        g_scratch[OFF_BIAS2 + c] = s;
    }
}

// ---------------- init accumulators ----------------
__global__ void k_init() {
    size_t stride = (size_t)gridDim.x * blockDim.x;
    size_t t0 = (size_t)blockIdx.x * blockDim.x + threadIdx.x;
    for (size_t i = t0; i < (size_t)NN * 128; i += stride)
        g_scratch[OFF_AGGR + i] = 0.f;
    for (size_t i = t0; i < (size_t)NN * 4; i += stride) {
        g_scratch[OFF_AMAX + i]  = -1e30f;
        g_scratch[OFF_DENOM + i] = 0.f;
    }
}

// ---------------- AdaGN (GroupNorm G=8 over D=128 + style modulation) ----------------
__global__ void __launch_bounds__(256) k_adagn(const float* __restrict__ hs,
                                               const float* __restrict__ gnw,
                                               const float* __restrict__ gnb, int M) {
    int n = blockIdx.x * 2 + (threadIdx.x >> 7);
    if (n >= M) return;
    int c = threadIdx.x & 127;
    float v = hs[(size_t)n * 128 + c];
    float s = v, q = v * v;
#pragma unroll
    for (int o = 8; o; o >>= 1) {
        s += __shfl_xor_sync(0xffffffffu, s, o, 16);
        q += __shfl_xor_sync(0xffffffffu, q, o, 16);
    }
    float mean = s * (1.f / 16.f);
    float var  = q * (1.f / 16.f) - mean * mean;
    float nv   = (v - mean) * rsqrtf(var + 1e-5f);
    float hm   = (nv * gnw[c] + gnb[c]) * (1.f + g_scratch[OFF_STYLE + c]) + g_scratch[OFF_STYLE + 128 + c];
    g_scratch[OFF_HMOD + (size_t)n * 128 + c] = hm;
}

// ---------------- generic K-tiled SGEMM: C[M x (128*gridDim.y)] = A[MxK] @ W[KxNout] + bias ----------------
// mode 0: plain; mode 1: GELU; mode 2: += extra (residual)
__global__ void __launch_bounds__(256) k_gemm(
    const float* __restrict__ A, int lda,
    const float* __restrict__ W, int ldw,
    const float* __restrict__ bias,
    float* __restrict__ C, int ldc,
    int M, int K, int mode, const float* __restrict__ extra)
{
    __shared__ __align__(16) float As[64 * 33];
    __shared__ __align__(16) float Ws[32 * 128];
    const int tid = threadIdx.x;
    const int tx = tid & 15;
    const int ty = tid >> 4;
    const int rowBase = blockIdx.x * 64;
    const int nBase = blockIdx.y * 128;

    float acc[4][8];
#pragma unroll
    for (int i = 0; i < 4; i++)
#pragma unroll
        for (int j = 0; j < 8; j++) acc[i][j] = 0.f;

    for (int kt = 0; kt < K; kt += 32) {
#pragma unroll
        for (int i = 0; i < 2; i++) {
            int f = tid + i * 256;
            int r = f >> 3;
            int k0 = (f & 7) << 2;
            int gr = rowBase + r;
            float4 v = make_float4(0.f, 0.f, 0.f, 0.f);
            if (gr < M) v = *(const float4*)&A[(size_t)gr * lda + kt + k0];
            As[r * 33 + k0 + 0] = v.x;
            As[r * 33 + k0 + 1] = v.y;
            As[r * 33 + k0 + 2] = v.z;
            As[r * 33 + k0 + 3] = v.w;
        }
#pragma unroll
        for (int i = 0; i < 4; i++) {
            int f = tid + i * 256;
            int kk = f >> 5;
            int c4 = (f & 31) << 2;
            *(float4*)&Ws[kk * 128 + c4] = *(const float4*)&W[(size_t)(kt + kk) * ldw + nBase + c4];
        }
        __syncthreads();
#pragma unroll
        for (int k = 0; k < 32; k++) {
            float a[4];
#pragma unroll
            for (int i = 0; i < 4; i++) a[i] = As[(ty * 4 + i) * 33 + k];
            float4 b0 = *(const float4*)&Ws[k * 128 + tx * 8];
            float4 b1 = *(const float4*)&Ws[k * 128 + tx * 8 + 4];
            float b[8] = {b0.x, b0.y, b0.z, b0.w, b1.x, b1.y, b1.z, b1.w};
#pragma unroll
            for (int i = 0; i < 4; i++)
#pragma unroll
                for (int j = 0; j < 8; j++) acc[i][j] += a[i] * b[j];
        }
        __syncthreads();
    }

#pragma unroll
    for (int i = 0; i < 4; i++) {
        int gr = rowBase + ty * 4 + i;
        if (gr < M) {
#pragma unroll
            for (int jj = 0; jj < 2; jj++) {
                int colg = nBase + tx * 8 + jj * 4;
                float4 bb = *(const float4*)&bias[colg];
                float4 v;
                v.x = acc[i][jj * 4 + 0] + bb.x;
                v.y = acc[i][jj * 4 + 1] + bb.y;
                v.z = acc[i][jj * 4 + 2] + bb.z;
                v.w = acc[i][jj * 4 + 3] + bb.w;
                if (mode == 1) {
                    v.x = geluf(v.x); v.y = geluf(v.y); v.z = geluf(v.z); v.w = geluf(v.w);
                } else if (mode == 2) {
                    float4 r4 = *(const float4*)&extra[(size_t)gr * 128 + colg];
                    v.x += r4.x; v.y += r4.y; v.z += r4.z; v.w += r4.w;
                }
                *(float4*)&C[(size_t)gr * ldc + colg] = v;
            }
        }
    }
}

// ---------------- combine: A = x_l + hWe ; B = x_r - hWe (in place within P) ----------------
__global__ void k_combine(int n32) {
    int stride = gridDim.x * blockDim.x;
    for (int i = blockIdx.x * blockDim.x + threadIdx.x; i < n32; i += stride) {
        int n = i >> 5, q = i & 31;
        float4* base = (float4*)(g_scratch + OFF_P) + (size_t)n * 96;
        float4 p0 = base[q], p1 = base[32 + q], p2 = base[64 + q];
        base[32 + q] = make_float4(p0.x + p2.x, p0.y + p2.y, p0.z + p2.z, p0.w + p2.w);
        base[64 + q] = make_float4(p1.x - p2.x, p1.y - p2.y, p1.z - p2.z, p1.w - p2.w);
    }
}

// ---------------- edge pass 1: logits + segment max (warp per edge) ----------------
__global__ void __launch_bounds__(256) k_logits(const int* __restrict__ ei,
                                                const float* __restrict__ pos,
                                                const float* __restrict__ We,
                                                const float* __restrict__ att, int E, int M) {
    int e = blockIdx.x * 8 + (threadIdx.x >> 5);
    if (e >= E) return;
    int l = threadIdx.x & 31;
    int is64 = g_is64;
    int s = eidx(ei, (size_t)e, is64, M);
    int d = eidx(ei, (size_t)E + e, is64, M);
    float2 ps = ((const float2*)pos)[s];
    float2 pd = ((const float2*)pos)[d];
    float rx = ps.x - pd.x, ry = ps.y - pd.y;
    float dsq = rx * rx + ry * ry + 1e-8f;
    float ox = -ry / dsq;   // ortho.x = -geom.y
    float oy =  rx / dsq;   // ortho.y =  geom.x
    float4 a4 = *(const float4*)(g_scratch + OFF_P + (size_t)s * 384 + 128 + 4 * l);
    float4 b4 = *(const float4*)(g_scratch + OFF_P + (size_t)d * 384 + 256 + 4 * l);
    float4 c0 = *(const float4*)(We + 128 * 128 + 4 * l);
    float4 c1 = *(const float4*)(We + 129 * 128 + 4 * l);
    float4 x;
    x.x = a4.x + b4.x + ox * c0.x + oy * c1.x;
    x.y = a4.y + b4.y + ox * c0.y + oy * c1.y;
    x.z = a4.z + b4.z + ox * c0.z + oy * c1.z;
    x.w = a4.w + b4.w + ox * c0.w + oy * c1.w;
    x.x = x.x > 0.f ? x.x : 0.2f * x.x;
    x.y = x.y > 0.f ? x.y : 0.2f * x.y;
    x.z = x.z > 0.f ? x.z : 0.2f * x.z;
    x.w = x.w > 0.f ? x.w : 0.2f * x.w;
    float4 at = *(const float4*)(att + 4 * l);
    float p = x.x * at.x + x.y * at.y + x.z * at.z + x.w * at.w;
    p += __shfl_xor_sync(0xffffffffu, p, 4);
    p += __shfl_xor_sync(0xffffffffu, p, 2);
    p += __shfl_xor_sync(0xffffffffu, p, 1);
    if ((l & 7) == 0) {
        int h = l >> 3;
        g_scratch[OFF_LOGIT + (size_t)e * 4 + h] = p;
        atomicMaxF(&g_scratch[OFF_AMAX + (size_t)d * 4 + h], p);
    }
}

// ---------------- edge pass 2: exp + segment sum (thread per edge) ----------------
__global__ void k_exp(const int* __restrict__ ei, int E, int M) {
    int e = blockIdx.x * blockDim.x + threadIdx.x;
    if (e >= E) return;
    int d = eidx(ei, (size_t)E + e, g_is64, M);
    float4 lg = *(const float4*)&g_scratch[OFF_LOGIT + (size_t)e * 4];
    float4 am = *(const float4*)&g_scratch[OFF_AMAX + (size_t)d * 4];
    float4 ex;
    ex.x = expf(lg.x - am.x);
    ex.y = expf(lg.y - am.y);
    ex.z = expf(lg.z - am.z);
    ex.w = expf(lg.w - am.w);
    *(float4*)&g_scratch[OFF_LOGIT + (size_t)e * 4] = ex;
    float* dn = &g_scratch[OFF_DENOM + (size_t)d * 4];
    atomicAdd(dn + 0, ex.x);
    atomicAdd(dn + 1, ex.y);
    atomicAdd(dn + 2, ex.z);
    atomicAdd(dn + 3, ex.w);
}

// ---------------- edge pass 3: weighted scatter (warp per edge, scalar REDG) ----------------
__global__ void __launch_bounds__(256) k_scatter(const int* __restrict__ ei, int E, int M) {
    int e = blockIdx.x * 8 + (threadIdx.x >> 5);
    if (e >= E) return;
    int l = threadIdx.x & 31;
    int is64 = g_is64;
    int s = eidx(ei, (size_t)e, is64, M);
    int d = eidx(ei, (size_t)E + e, is64, M);
    float4 ex = *(const float4*)&g_scratch[OFF_LOGIT + (size_t)e * 4];
    float4 dn = *(const float4*)&g_scratch[OFF_DENOM + (size_t)d * 4];
    float a0 = ex.x / (dn.x + 1e-16f);
    float a1 = ex.y / (dn.y + 1e-16f);
    float a2 = ex.z / (dn.z + 1e-16f);
    float a3 = ex.w / (dn.w + 1e-16f);
    int h = l >> 3;
    float al = (h < 2) ? (h == 0 ? a0 : a1) : (h == 2 ? a2 : a3);
    float4 xl = *(const float4*)(g_scratch + OFF_P + (size_t)s * 384 + 4 * l);
    float* dst = g_scratch + OFF_AGGR + (size_t)d * 128 + 4 * l;
    atomicAdd(dst + 0, xl.x * al);
    atomicAdd(dst + 1, xl.y * al);
    atomicAdd(dst + 2, xl.z * al);
    atomicAdd(dst + 3, xl.w * al);
}

// ---------------- LayerNorm (warp per node) ----------------
__global__ void __launch_bounds__(256) k_ln(const float* __restrict__ lnw,
                                            const float* __restrict__ lnb, int M) {
    int n = blockIdx.x * 8 + (threadIdx.x >> 5);
    if (n >= M) return;
    int l = threadIdx.x & 31;
    float4 v = ((const float4*)(g_scratch + OFF_AGGR2 + (size_t)n * 128))[l];
    float s = v.x + v.y + v.z + v.w;
    float q = v.x * v.x + v.y * v.y + v.z * v.z + v.w * v.w;
#pragma unroll
    for (int o = 16; o; o >>= 1) {
        s += __shfl_xor_sync(0xffffffffu, s, o);
        q += __shfl_xor_sync(0xffffffffu, q, o);
    }
    float mean = s * (1.f / 128.f);
    float var  = q * (1.f / 128.f) - mean * mean;
    float rstd = rsqrtf(var + 1e-5f);
    float4 w = ((const float4*)lnw)[l];
    float4 b = ((const float4*)lnb)[l];
    float4 o4;
    o4.x = (v.x - mean) * rstd * w.x + b.x;
    o4.y = (v.y - mean) * rstd * w.y + b.y;
    o4.z = (v.z - mean) * rstd * w.z + b.z;
    o4.w = (v.w - mean) * rstd * w.w + b.w;
    ((float4*)(g_scratch + OFF_HMOD + (size_t)n * 128))[l] = o4;
}

// ---------------- launch ----------------
extern "C" void kernel_launch(void* const* d_in, const int* in_sizes, int n_in,
                              void* d_out, int out_size) {
    const float* h_target = (const float*)d_in[0];
    const float* h_source = (const float*)d_in[1];
    const int* ei      = (const int*)d_in[2];
    const float* pos   = (const float*)d_in[3];
    const float* t_emb = (const float*)d_in[4];
    const float* gn_w  = (const float*)d_in[5];
    const float* gn_b  = (const float*)d_in[6];
    const float* fcW   = (const float*)d_in[7];
    const float* fcb   = (const float*)d_in[8];
    const float* Wl    = (const float*)d_in[9];
    const float* bl    = (const float*)d_in[10];
    const float* Wr    = (const float*)d_in[11];
    const float* br    = (const float*)d_in[12];
    const float* We    = (const float*)d_in[13];
    const float* att   = (const float*)d_in[14];
    const float* gatb  = (const float*)d_in[15];
    const float* Wp    = (const float*)d_in[16];
    const float* bp    = (const float*)d_in[17];
    const float* lnw   = (const float*)d_in[18];
    const float* lnb   = (const float*)d_in[19];
    const float* W1    = (const float*)d_in[20];
    const float* b1    = (const float*)d_in[21];
    const float* W2    = (const float*)d_in[22];
    const float* b2    = (const float*)d_in[23];

    int M = in_sizes[0] / 128; if (M > NN) M = NN;
    int E = in_sizes[2] / 2;   if (E > EE) E = EE;

    float* sc = nullptr;
    cudaGetSymbolAddress((void**)&sc, g_scratch);
    float* P     = sc + OFF_P;
    float* HM    = sc + OFF_HMOD;
    float* AGGR  = sc + OFF_AGGR;
    float* AGGR2 = sc + OFF_AGGR2;
    float* BIAS2 = sc + OFF_BIAS2;
    float* ZERO  = sc + OFF_ZERO;

    dim3 blk(256);
    dim3 g1((M + 63) / 64, 1);
    dim3 g3((M + 63) / 64, 2);

    k_detect<<<1, 1>>>(ei);
    k_style<<<1, 384>>>(t_emb, fcW, fcb, gatb, Wp, bp);
    k_init<<<2048, 256>>>();
    k_adagn<<<(M + 1) / 2, 256>>>(h_source, gn_w, gn_b, M);

    // fused node transforms: x_l = h@Wl+bl ; x_r = h@Wr+br ; hWe = h@We[:128]
    k_gemm<<<g1, blk>>>(HM, 128, Wl, 128, bl,   P,       384, M, 128, 0, nullptr);
    k_gemm<<<g1, blk>>>(HM, 128, Wr, 128, br,   P + 128, 384, M, 128, 0, nullptr);
    k_gemm<<<g1, blk>>>(HM, 128, We, 128, ZERO, P + 256, 384, M, 128, 0, nullptr);
    k_combine<<<2048, 256>>>(M * 32);

    k_logits<<<(E + 7) / 8, 256>>>(ei, pos, We, att, E, M);
    k_exp<<<(E + 255) / 256, 256>>>(ei, E, M);
    k_scatter<<<(E + 7) / 8, 256>>>(ei, E, M);

    // post_gat: (out + gat_b)@Wp + bp  == out@Wp + bias2
    k_gemm<<<g1, blk>>>(AGGR, 128, Wp, 128, BIAS2, AGGR2, 128, M, 128, 0, nullptr);
    k_ln<<<(M + 7) / 8, 256>>>(lnw, lnb, M);
    // update MLP: GELU(LN@W1+b1)@W2+b2 + h_target
    k_gemm<<<g3, blk>>>(HM, 128, W1, 256, b1, P, 256, M, 128, 1, nullptr);
    k_gemm<<<g1, blk>>>(P, 256, W2, 128, b2, (float*)d_out, 128, M, 256, 2, h_target);
}

// round 9
// speedup vs baseline: 1.2874x; 1.2874x over previous
#include <cuda_runtime.h>

#define NN 50000
#define EE 800000

// ---------------- scratch layout (floats) ----------------
constexpr size_t OFF_P     = 0;                              // N*384: [x_l | A | B]; later reused as z1 (N*256)
constexpr size_t OFF_HMOD  = OFF_P     + (size_t)NN * 384;   // N*128: h_mod; later reused as LN output
constexpr size_t OFF_LOGIT = OFF_HMOD  + (size_t)NN * 128;   // E*4: logits
constexpr size_t OFF_AMAX  = OFF_LOGIT + (size_t)EE * 4;     // N*4
constexpr size_t OFF_DENOM = OFF_AMAX  + (size_t)NN * 4;     // N*4
constexpr size_t OFF_AGGR  = OFF_DENOM + (size_t)NN * 4;     // N*128 (GAT out, atomically accumulated)
constexpr size_t OFF_AGGR2 = OFF_AGGR  + (size_t)NN * 128;   // N*128 (x_r temp, then Wp output)
constexpr size_t OFF_STYLE = OFF_AGGR2 + (size_t)NN * 128;   // 256 (gamma|beta)
constexpr size_t OFF_BIAS2 = OFF_STYLE + 256;                // 128 (gat_b@Wp + bp)
constexpr size_t OFF_ZERO  = OFF_BIAS2 + 128;                // 128 zeros (never written)
constexpr size_t SCRATCH_TOTAL = OFF_ZERO + 128;

__device__ __align__(16) float g_scratch[SCRATCH_TOTAL];
__device__ int g_is64;   // 1 if edge_index buffer is int64, 0 if int32

// ---------------- helpers ----------------
__device__ __forceinline__ float geluf(float x) {
    return 0.5f * x * (1.f + erff(x * 0.70710678118654752440f));
}

__device__ __forceinline__ void atomicMaxF(float* addr, float v) {
    if (v >= 0.f) atomicMax((int*)addr, __float_as_int(v));
    else          atomicMin((unsigned int*)addr, __float_as_uint(v));
}

__device__ __forceinline__ int eidx(const int* __restrict__ ei32, size_t pos, int is64, int M) {
    int v = ei32[is64 ? (pos << 1) : pos];
    if ((unsigned)v >= (unsigned)M) v = 0;
    return v;
}

// ---------------- detect edge_index dtype ----------------
__global__ void k_detect(const int* __restrict__ ei32) {
    int z = 0;
#pragma unroll
    for (int i = 0; i < 16; i++) z |= ei32[2 * i + 1];
    g_is64 = (z == 0) ? 1 : 0;
}

// ---------------- tiny precompute ----------------
__global__ void k_style(const float* __restrict__ t_emb, const float* __restrict__ fcW,
                        const float* __restrict__ fcb, const float* __restrict__ gatb,
                        const float* __restrict__ Wp, const float* __restrict__ bp) {
    int j = threadIdx.x;
    if (j < 256) {
        float s = fcb[j];
        for (int i = 0; i < 128; i++) s += t_emb[i] * fcW[i * 256 + j];
        g_scratch[OFF_STYLE + j] = s;
    } else if (j < 384) {
        int c = j - 256;
        float s = bp[c];
        for (int i = 0; i < 128; i++) s += gatb[i] * Wp[i * 128 + c];
        g_scratch[OFF_BIAS2 + c] = s;
    }
}

// ---------------- init accumulators ----------------
__global__ void k_init() {
    size_t stride = (size_t)gridDim.x * blockDim.x;
    size_t t0 = (size_t)blockIdx.x * blockDim.x + threadIdx.x;
    for (size_t i = t0; i < (size_t)NN * 128; i += stride)
        g_scratch[OFF_AGGR + i] = 0.f;
    for (size_t i = t0; i < (size_t)NN * 4; i += stride) {
        g_scratch[OFF_AMAX + i]  = -1e30f;
        g_scratch[OFF_DENOM + i] = 0.f;
    }
}

// ---------------- AdaGN ----------------
__global__ void __launch_bounds__(256) k_adagn(const float* __restrict__ hs,
                                               const float* __restrict__ gnw,
                                               const float* __restrict__ gnb, int M) {
    int n = blockIdx.x * 2 + (threadIdx.x >> 7);
    if (n >= M) return;
    int c = threadIdx.x & 127;
    float v = hs[(size_t)n * 128 + c];
    float s = v, q = v * v;
#pragma unroll
    for (int o = 8; o; o >>= 1) {
        s += __shfl_xor_sync(0xffffffffu, s, o, 16);
        q += __shfl_xor_sync(0xffffffffu, q, o, 16);
    }
    float mean = s * (1.f / 16.f);
    float var  = q * (1.f / 16.f) - mean * mean;
    float nv   = (v - mean) * rsqrtf(var + 1e-5f);
    float hm   = (nv * gnw[c] + gnb[c]) * (1.f + g_scratch[OFF_STYLE + c]) + g_scratch[OFF_STYLE + 128 + c];
    g_scratch[OFF_HMOD + (size_t)n * 128 + c] = hm;
}

// ---------------- 128x128 SGEMM, K-step 16, register double buffer ----------------
// mode 0: C = acc + bias
// mode 1: C = GELU(acc + bias)
// mode 2: C = acc + bias + extra   (extra ld=128, residual)
// mode 3: combine: xl = C[gr*ldc + col], xr = extra[gr*128 + col];
//         C[gr*ldc + 128 + col] = xl + acc ; C[gr*ldc + 256 + col] = xr - acc
__global__ void __launch_bounds__(256, 2) k_gemm(
    const float* __restrict__ A, int lda,
    const float* __restrict__ W, int ldw,
    const float* __restrict__ bias,
    float* __restrict__ C, int ldc,
    int M, int K, int mode, const float* __restrict__ extra)
{
    __shared__ __align__(16) float As[16][132];
    __shared__ __align__(16) float Ws[16][128];
    const int tid = threadIdx.x;
    const int tx = tid & 15;
    const int ty = tid >> 4;
    const int rowBase = blockIdx.x * 128;
    const int nBase = blockIdx.y * 128;

    float acc[8][8];
#pragma unroll
    for (int i = 0; i < 8; i++)
#pragma unroll
        for (int j = 0; j < 8; j++) acc[i][j] = 0.f;

    float4 aReg[2], wReg[2];

    // prefetch first tile
#pragma unroll
    for (int i = 0; i < 2; i++) {
        int idx = tid * 2 + i;
        int m = idx >> 2, k4 = (idx & 3) << 2;
        int gr = rowBase + m;
        aReg[i] = (gr < M) ? *(const float4*)&A[(size_t)gr * lda + k4]
                           : make_float4(0.f, 0.f, 0.f, 0.f);
        int kk = idx >> 5, c4 = (idx & 31) << 2;
        wReg[i] = *(const float4*)&W[(size_t)kk * ldw + nBase + c4];
    }

    for (int kt = 0; kt < K; kt += 16) {
        // commit prefetched tile to smem
#pragma unroll
        for (int i = 0; i < 2; i++) {
            int idx = tid * 2 + i;
            int m = idx >> 2, k4 = (idx & 3) << 2;
            As[k4 + 0][m] = aReg[i].x;
            As[k4 + 1][m] = aReg[i].y;
            As[k4 + 2][m] = aReg[i].z;
            As[k4 + 3][m] = aReg[i].w;
            int kk = idx >> 5, c4 = (idx & 31) << 2;
            *(float4*)&Ws[kk][c4] = wReg[i];
        }
        __syncthreads();
        // prefetch next tile
        if (kt + 16 < K) {
#pragma unroll
            for (int i = 0; i < 2; i++) {
                int idx = tid * 2 + i;
                int m = idx >> 2, k4 = (idx & 3) << 2;
                int gr = rowBase + m;
                aReg[i] = (gr < M) ? *(const float4*)&A[(size_t)gr * lda + kt + 16 + k4]
                                   : make_float4(0.f, 0.f, 0.f, 0.f);
                int kk = idx >> 5, c4 = (idx & 31) << 2;
                wReg[i] = *(const float4*)&W[(size_t)(kt + 16 + kk) * ldw + nBase + c4];
            }
        }
#pragma unroll
        for (int k = 0; k < 16; k++) {
            float a[8], b[8];
            *(float4*)&a[0] = *(const float4*)&As[k][ty * 8];
            *(float4*)&a[4] = *(const float4*)&As[k][ty * 8 + 4];
            *(float4*)&b[0] = *(const float4*)&Ws[k][tx * 8];
            *(float4*)&b[4] = *(const float4*)&Ws[k][tx * 8 + 4];
#pragma unroll
            for (int i = 0; i < 8; i++)
#pragma unroll
                for (int j = 0; j < 8; j++) acc[i][j] += a[i] * b[j];
        }
        __syncthreads();
    }

#pragma unroll
    for (int i = 0; i < 8; i++) {
        int gr = rowBase + ty * 8 + i;
        if (gr >= M) break;
#pragma unroll
        for (int jj = 0; jj < 2; jj++) {
            int colg = nBase + tx * 8 + jj * 4;
            float4 bb = *(const float4*)&bias[colg];
            float4 v;
            v.x = acc[i][jj * 4 + 0] + bb.x;
            v.y = acc[i][jj * 4 + 1] + bb.y;
            v.z = acc[i][jj * 4 + 2] + bb.z;
            v.w = acc[i][jj * 4 + 3] + bb.w;
            if (mode == 0) {
                *(float4*)&C[(size_t)gr * ldc + colg] = v;
            } else if (mode == 1) {
                v.x = geluf(v.x); v.y = geluf(v.y); v.z = geluf(v.z); v.w = geluf(v.w);
                *(float4*)&C[(size_t)gr * ldc + colg] = v;
            } else if (mode == 2) {
                float4 r4 = *(const float4*)&extra[(size_t)gr * 128 + colg];
                v.x += r4.x; v.y += r4.y; v.z += r4.z; v.w += r4.w;
                *(float4*)&C[(size_t)gr * ldc + colg] = v;
            } else {
                float4 xl = *(const float4*)&C[(size_t)gr * ldc + colg];
                float4 xr = *(const float4*)&extra[(size_t)gr * 128 + colg];
                float4 A4 = make_float4(xl.x + v.x, xl.y + v.y, xl.z + v.z, xl.w + v.w);
                float4 B4 = make_float4(xr.x - v.x, xr.y - v.y, xr.z - v.z, xr.w - v.w);
                *(float4*)&C[(size_t)gr * ldc + 128 + colg] = A4;
                *(float4*)&C[(size_t)gr * ldc + 256 + colg] = B4;
            }
        }
    }
}

// ---------------- edge pass 1: logits + segment max (warp per edge) ----------------
__global__ void __launch_bounds__(256) k_logits(const int* __restrict__ ei,
                                                const float* __restrict__ pos,
                                                const float* __restrict__ We,
                                                const float* __restrict__ att, int E, int M) {
    int e = blockIdx.x * 8 + (threadIdx.x >> 5);
    if (e >= E) return;
    int l = threadIdx.x & 31;
    int is64 = g_is64;
    int s = eidx(ei, (size_t)e, is64, M);
    int d = eidx(ei, (size_t)E + e, is64, M);
    float2 ps = ((const float2*)pos)[s];
    float2 pd = ((const float2*)pos)[d];
    float rx = ps.x - pd.x, ry = ps.y - pd.y;
    float dsq = rx * rx + ry * ry + 1e-8f;
    float ox = -ry / dsq;
    float oy =  rx / dsq;
    float4 a4 = *(const float4*)(g_scratch + OFF_P + (size_t)s * 384 + 128 + 4 * l);
    float4 b4 = *(const float4*)(g_scratch + OFF_P + (size_t)d * 384 + 256 + 4 * l);
    float4 c0 = *(const float4*)(We + 128 * 128 + 4 * l);
    float4 c1 = *(const float4*)(We + 129 * 128 + 4 * l);
    float4 x;
    x.x = a4.x + b4.x + ox * c0.x + oy * c1.x;
    x.y = a4.y + b4.y + ox * c0.y + oy * c1.y;
    x.z = a4.z + b4.z + ox * c0.z + oy * c1.z;
    x.w = a4.w + b4.w + ox * c0.w + oy * c1.w;
    x.x = x.x > 0.f ? x.x : 0.2f * x.x;
    x.y = x.y > 0.f ? x.y : 0.2f * x.y;
    x.z = x.z > 0.f ? x.z : 0.2f * x.z;
    x.w = x.w > 0.f ? x.w : 0.2f * x.w;
    float4 at = *(const float4*)(att + 4 * l);
    float p = x.x * at.x + x.y * at.y + x.z * at.z + x.w * at.w;
    p += __shfl_xor_sync(0xffffffffu, p, 4);
    p += __shfl_xor_sync(0xffffffffu, p, 2);
    p += __shfl_xor_sync(0xffffffffu, p, 1);
    if ((l & 7) == 0) {
        int h = l >> 3;
        g_scratch[OFF_LOGIT + (size_t)e * 4 + h] = p;
        atomicMaxF(&g_scratch[OFF_AMAX + (size_t)d * 4 + h], p);
    }
}

// ---------------- edge pass 2: exp + unnormalized scatter (warp per edge, v4 RED) ----------------
__global__ void __launch_bounds__(256) k_scat(const int* __restrict__ ei, int E, int M) {
    int e = blockIdx.x * 8 + (threadIdx.x >> 5);
    if (e >= E) return;
    int l = threadIdx.x & 31;
    int is64 = g_is64;
    int s = eidx(ei, (size_t)e, is64, M);
    int d = eidx(ei, (size_t)E + e, is64, M);
    float4 lg = *(const float4*)&g_scratch[OFF_LOGIT + (size_t)e * 4];
    float4 am = *(const float4*)&g_scratch[OFF_AMAX + (size_t)d * 4];
    int h = l >> 3;
    float lgh = (h < 2) ? (h == 0 ? lg.x : lg.y) : (h == 2 ? lg.z : lg.w);
    float amh = (h < 2) ? (h == 0 ? am.x : am.y) : (h == 2 ? am.z : am.w);
    float eh = expf(lgh - amh);
    float e0 = __shfl_sync(0xffffffffu, eh, 0);
    float e1 = __shfl_sync(0xffffffffu, eh, 8);
    float e2 = __shfl_sync(0xffffffffu, eh, 16);
    float e3 = __shfl_sync(0xffffffffu, eh, 24);
    if (l == 0)
        atomicAdd((float4*)&g_scratch[OFF_DENOM + (size_t)d * 4], make_float4(e0, e1, e2, e3));
    float4 xl = *(const float4*)(g_scratch + OFF_P + (size_t)s * 384 + 4 * l);
    atomicAdd((float4*)(g_scratch + OFF_AGGR + (size_t)d * 128 + 4 * l),
              make_float4(xl.x * eh, xl.y * eh, xl.z * eh, xl.w * eh));
}

// ---------------- normalize aggregated messages per (node, head) ----------------
__global__ void __launch_bounds__(256) k_norm(int M) {
    int n = blockIdx.x * 8 + (threadIdx.x >> 5);
    if (n >= M) return;
    int l = threadIdx.x & 31;
    int h = l >> 3;
    float dn = g_scratch[OFF_DENOM + (size_t)n * 4 + h];
    float r = 1.f / (dn + 1e-16f);
    float4* p = (float4*)(g_scratch + OFF_AGGR + (size_t)n * 128) + l;
    float4 v = *p;
    v.x *= r; v.y *= r; v.z *= r; v.w *= r;
    *p = v;
}

// ---------------- LayerNorm (warp per node) ----------------
__global__ void __launch_bounds__(256) k_ln(const float* __restrict__ lnw,
                                            const float* __restrict__ lnb, int M) {
    int n = blockIdx.x * 8 + (threadIdx.x >> 5);
    if (n >= M) return;
    int l = threadIdx.x & 31;
    float4 v = ((const float4*)(g_scratch + OFF_AGGR2 + (size_t)n * 128))[l];
    float s = v.x + v.y + v.z + v.w;
    float q = v.x * v.x + v.y * v.y + v.z * v.z + v.w * v.w;
#pragma unroll
    for (int o = 16; o; o >>= 1) {
        s += __shfl_xor_sync(0xffffffffu, s, o);
        q += __shfl_xor_sync(0xffffffffu, q, o);
    }
    float mean = s * (1.f / 128.f);
    float var  = q * (1.f / 128.f) - mean * mean;
    float rstd = rsqrtf(var + 1e-5f);
    float4 w = ((const float4*)lnw)[l];
    float4 b = ((const float4*)lnb)[l];
    float4 o4;
    o4.x = (v.x - mean) * rstd * w.x + b.x;
    o4.y = (v.y - mean) * rstd * w.y + b.y;
    o4.z = (v.z - mean) * rstd * w.z + b.z;
    o4.w = (v.w - mean) * rstd * w.w + b.w;
    ((float4*)(g_scratch + OFF_HMOD + (size_t)n * 128))[l] = o4;
}

// ---------------- launch ----------------
extern "C" void kernel_launch(void* const* d_in, const int* in_sizes, int n_in,
                              void* d_out, int out_size) {
    const float* h_target = (const float*)d_in[0];
    const float* h_source = (const float*)d_in[1];
    const int* ei      = (const int*)d_in[2];
    const float* pos   = (const float*)d_in[3];
    const float* t_emb = (const float*)d_in[4];
    const float* gn_w  = (const float*)d_in[5];
    const float* gn_b  = (const float*)d_in[6];
    const float* fcW   = (const float*)d_in[7];
    const float* fcb   = (const float*)d_in[8];
    const float* Wl    = (const float*)d_in[9];
    const float* bl    = (const float*)d_in[10];
    const float* Wr    = (const float*)d_in[11];
    const float* br    = (const float*)d_in[12];
    const float* We    = (const float*)d_in[13];
    const float* att   = (const float*)d_in[14];
    const float* gatb  = (const float*)d_in[15];
    const float* Wp    = (const float*)d_in[16];
    const float* bp    = (const float*)d_in[17];
    const float* lnw   = (const float*)d_in[18];
    const float* lnb   = (const float*)d_in[19];
    const float* W1    = (const float*)d_in[20];
    const float* b1    = (const float*)d_in[21];
    const float* W2    = (const float*)d_in[22];
    const float* b2    = (const float*)d_in[23];

    int M = in_sizes[0] / 128; if (M > NN) M = NN;
    int E = in_sizes[2] / 2;   if (E > EE) E = EE;

    float* sc = nullptr;
    cudaGetSymbolAddress((void**)&sc, g_scratch);
    float* P     = sc + OFF_P;
    float* HM    = sc + OFF_HMOD;
    float* AGGR  = sc + OFF_AGGR;
    float* AGGR2 = sc + OFF_AGGR2;
    float* BIAS2 = sc + OFF_BIAS2;
    float* ZERO  = sc + OFF_ZERO;

    dim3 blk(256);
    dim3 g1((M + 127) / 128, 1);
    dim3 g2((M + 127) / 128, 2);

    k_detect<<<1, 1>>>(ei);
    k_style<<<1, 384>>>(t_emb, fcW, fcb, gatb, Wp, bp);
    k_init<<<2048, 256>>>();
    k_adagn<<<(M + 1) / 2, 256>>>(h_source, gn_w, gn_b, M);

    // node transforms: x_l -> P+0 ; x_r -> AGGR2 (temp) ; hWe fused-combine -> P+128 / P+256
    k_gemm<<<g1, blk>>>(HM, 128, Wl, 128, bl,   P,     384, M, 128, 0, nullptr);
    k_gemm<<<g1, blk>>>(HM, 128, Wr, 128, br,   AGGR2, 128, M, 128, 0, nullptr);
    k_gemm<<<g1, blk>>>(HM, 128, We, 128, ZERO, P,     384, M, 128, 3, AGGR2);

    k_logits<<<(E + 7) / 8, 256>>>(ei, pos, We, att, E, M);
    k_scat<<<(E + 7) / 8, 256>>>(ei, E, M);
    k_norm<<<(M + 7) / 8, 256>>>(M);

    // post_gat: aggr@Wp + (gat_b@Wp + bp)
    k_gemm<<<g1, blk>>>(AGGR, 128, Wp, 128, BIAS2, AGGR2, 128, M, 128, 0, nullptr);
    k_ln<<<(M + 7) / 8, 256>>>(lnw, lnb, M);
    // update MLP: GELU(LN@W1+b1)@W2+b2 + h_target
    k_gemm<<<g2, blk>>>(HM, 128, W1, 256, b1, P, 256, M, 128, 1, nullptr);
    k_gemm<<<g1, blk>>>(P, 256, W2, 128, b2, (float*)d_out, 128, M, 256, 2, h_target);
}

// round 12
// speedup vs baseline: 1.6363x; 1.2710x over previous
#include <cuda_runtime.h>
#include <cuda_bf16.h>
#include <cstdint>
#include <cstddef>

#define NN 50000
#define EE 800000

// ---------------- scratch layout (floats) ----------------
constexpr size_t OFF_P     = 0;                              // N*384: [x_l | A | B]; later reused as z1 (N*256)
constexpr size_t OFF_HMOD  = OFF_P     + (size_t)NN * 384;   // N*128: h_mod; later reused as LN output
constexpr size_t OFF_LOGIT = OFF_HMOD  + (size_t)NN * 128;   // E*4: logits
constexpr size_t OFF_AMAX  = OFF_LOGIT + (size_t)EE * 4;     // N*4
constexpr size_t OFF_DENOM = OFF_AMAX  + (size_t)NN * 4;     // N*4
constexpr size_t OFF_AGGR  = OFF_DENOM + (size_t)NN * 4;     // N*128 (GAT out, atomically accumulated)
constexpr size_t OFF_AGGR2 = OFF_AGGR  + (size_t)NN * 128;   // N*128 (x_r temp, then Wp output)
constexpr size_t OFF_STYLE = OFF_AGGR2 + (size_t)NN * 128;   // 256 (gamma|beta)
constexpr size_t OFF_BIAS2 = OFF_STYLE + 256;                // 128 (gat_b@Wp + bp)
constexpr size_t OFF_ZERO  = OFF_BIAS2 + 128;                // 128 zeros (never written)
constexpr size_t SCRATCH_TOTAL = OFF_ZERO + 128;

__device__ __align__(16) float g_scratch[SCRATCH_TOTAL];
__device__ int g_is64;

// ---------------- helpers ----------------
__device__ __forceinline__ float geluf(float x) {
    return 0.5f * x * (1.f + erff(x * 0.70710678118654752440f));
}
__device__ __forceinline__ void atomicMaxF(float* addr, float v) {
    if (v >= 0.f) atomicMax((int*)addr, __float_as_int(v));
    else          atomicMin((unsigned int*)addr, __float_as_uint(v));
}
__device__ __forceinline__ int eidx(const int* __restrict__ ei32, size_t pos, int is64, int M) {
    int v = ei32[is64 ? (pos << 1) : pos];
    if ((unsigned)v >= (unsigned)M) v = 0;
    return v;
}
__device__ __forceinline__ uint32_t s2u(const void* p) {
    uint32_t a;
    asm("{ .reg .u64 t; cvta.to.shared.u64 t, %1; cvt.u32.u64 %0, t; }" : "=r"(a) : "l"(p));
    return a;
}
__device__ __forceinline__ void ldsm_x4(uint32_t& r0, uint32_t& r1, uint32_t& r2, uint32_t& r3, uint32_t addr) {
    asm volatile("ldmatrix.sync.aligned.m8n8.x4.shared.b16 {%0,%1,%2,%3}, [%4];"
                 : "=r"(r0), "=r"(r1), "=r"(r2), "=r"(r3) : "r"(addr));
}
__device__ __forceinline__ void ldsm_x2(uint32_t& r0, uint32_t& r1, uint32_t addr) {
    asm volatile("ldmatrix.sync.aligned.m8n8.x2.shared.b16 {%0,%1}, [%2];"
                 : "=r"(r0), "=r"(r1) : "r"(addr));
}
__device__ __forceinline__ void mma_bf16(float* c, uint32_t a0, uint32_t a1, uint32_t a2, uint32_t a3,
                                         uint32_t b0, uint32_t b1) {
    asm volatile("mma.sync.aligned.m16n8k16.row.col.f32.bf16.bf16.f32 "
                 "{%0,%1,%2,%3}, {%4,%5,%6,%7}, {%8,%9}, {%0,%1,%2,%3};"
                 : "+f"(c[0]), "+f"(c[1]), "+f"(c[2]), "+f"(c[3])
                 : "r"(a0), "r"(a1), "r"(a2), "r"(a3), "r"(b0), "r"(b1));
}
__device__ __forceinline__ uint32_t pack_split(float a, float b, uint32_t& lo) {
    __nv_bfloat16 ha = __float2bfloat16(a), hb = __float2bfloat16(b);
    float ra = a - __bfloat162float(ha), rb = b - __bfloat162float(hb);
    __nv_bfloat16 la = __float2bfloat16(ra), lb = __float2bfloat16(rb);
    unsigned short uha = *(unsigned short*)&ha, uhb = *(unsigned short*)&hb;
    unsigned short ula = *(unsigned short*)&la, ulb = *(unsigned short*)&lb;
    lo = (uint32_t)ula | ((uint32_t)ulb << 16);
    return (uint32_t)uha | ((uint32_t)uhb << 16);
}

// ---------------- detect edge_index dtype ----------------
__global__ void k_detect(const int* __restrict__ ei32) {
    int z = 0;
#pragma unroll
    for (int i = 0; i < 16; i++) z |= ei32[2 * i + 1];
    g_is64 = (z == 0) ? 1 : 0;
}

// ---------------- tiny precompute ----------------
__global__ void k_style(const float* __restrict__ t_emb, const float* __restrict__ fcW,
                        const float* __restrict__ fcb, const float* __restrict__ gatb,
                        const float* __restrict__ Wp, const float* __restrict__ bp) {
    int j = threadIdx.x;
    if (j < 256) {
        float s = fcb[j];
        for (int i = 0; i < 128; i++) s += t_emb[i] * fcW[i * 256 + j];
        g_scratch[OFF_STYLE + j] = s;
    } else if (j < 384) {
        int c = j - 256;
        float s = bp[c];
        for (int i = 0; i < 128; i++) s += gatb[i] * Wp[i * 128 + c];
        g_scratch[OFF_BIAS2 + c] = s;
    }
}

// ---------------- init accumulators ----------------
__global__ void k_init() {
    size_t stride = (size_t)gridDim.x * blockDim.x;
    size_t t0 = (size_t)blockIdx.x * blockDim.x + threadIdx.x;
    for (size_t i = t0; i < (size_t)NN * 128; i += stride)
        g_scratch[OFF_AGGR + i] = 0.f;
    for (size_t i = t0; i < (size_t)NN * 4; i += stride) {
        g_scratch[OFF_AMAX + i]  = -1e30f;
        g_scratch[OFF_DENOM + i] = 0.f;
    }
}

// ---------------- AdaGN ----------------
__global__ void __launch_bounds__(256) k_adagn(const float* __restrict__ hs,
                                               const float* __restrict__ gnw,
                                               const float* __restrict__ gnb, int M) {
    int n = blockIdx.x * 2 + (threadIdx.x >> 7);
    if (n >= M) return;
    int c = threadIdx.x & 127;
    float v = hs[(size_t)n * 128 + c];
    float s = v, q = v * v;
#pragma unroll
    for (int o = 8; o; o >>= 1) {
        s += __shfl_xor_sync(0xffffffffu, s, o, 16);
        q += __shfl_xor_sync(0xffffffffu, q, o, 16);
    }
    float mean = s * (1.f / 16.f);
    float var  = q * (1.f / 16.f) - mean * mean;
    float nv   = (v - mean) * rsqrtf(var + 1e-5f);
    float hm   = (nv * gnw[c] + gnb[c]) * (1.f + g_scratch[OFF_STYLE + c]) + g_scratch[OFF_STYLE + 128 + c];
    g_scratch[OFF_HMOD + (size_t)n * 128 + c] = hm;
}

// ======================================================================
// HMMA bf16 3-term split GEMM: C[128 x 128-tile] = A[MxK]@W[KxN] + bias
// mma.sync m16n8k16 row.col; A hi/lo and B(=W^T) hi/lo in smem.
// modes: 0 plain, 1 GELU, 2 +extra residual, 3 combine (A=xl+acc, B=xr-acc)
// ======================================================================
constexpr int SLDA  = 136;                 // halves per smem row (conflict-free ldmatrix)
constexpr int TILEH = 128 * SLDA;          // halves per 128x128 tile
constexpr int AHI_H = 0;
constexpr int ALO_H = TILEH;
constexpr int BHI_H = 2 * TILEH;
constexpr int BLO_H = 3 * TILEH;
constexpr int SMEM_BYTES = 4 * TILEH * 2;  // 139264

__global__ void __launch_bounds__(256, 1) k_mma(
    const float* __restrict__ A, int lda,
    const float* __restrict__ W, int ldw,
    const float* __restrict__ bias,
    float* __restrict__ C, int ldc,
    int M, int K, int mode, const float* __restrict__ extra)
{
    extern __shared__ __align__(16) char dsm[];
    const int tid = threadIdx.x;
    const int w = tid >> 5;
    const int lane = tid & 31;
    const uint32_t sb = s2u(dsm);

    const int rowBase = blockIdx.x * 128;
    const int nBase = blockIdx.y * 128;
    const int wm = w & 1;      // 0..1 : 64-row half
    const int wn = w >> 1;     // 0..3 : 32-col quarter

    float c[4][4][4];
#pragma unroll
    for (int i = 0; i < 4; i++)
#pragma unroll
        for (int j = 0; j < 4; j++)
#pragma unroll
            for (int q = 0; q < 4; q++) c[i][j][q] = 0.f;

    const int lrA = lane & 15, lcA = (lane >> 4) << 3;
    const int lrB = lane & 7,  lcB = ((lane >> 3) & 1) << 3;

    for (int kt = 0; kt < K; kt += 128) {
        // ---- A chunk: 128x128 fp32 -> bf16 hi/lo ----
#pragma unroll
        for (int it = 0; it < 16; it++) {
            int s = it * 256 + tid;
            int row = s >> 5, col = (s & 31) * 4;
            int gr = rowBase + row;
            float4 v = make_float4(0.f, 0.f, 0.f, 0.f);
            if (gr < M) v = *(const float4*)&A[(size_t)gr * lda + kt + col];
            uint32_t l0, l1;
            uint32_t h0 = pack_split(v.x, v.y, l0);
            uint32_t h1 = pack_split(v.z, v.w, l1);
            int ho = row * SLDA + col;
            *(uint2*)(dsm + 2 * (AHI_H + ho)) = make_uint2(h0, h1);
            *(uint2*)(dsm + 2 * (ALO_H + ho)) = make_uint2(l0, l1);
        }
        // ---- B chunk: Bs[n][k] = W[kt+k][nBase+n], bf16 hi/lo ----
#pragma unroll
        for (int it = 0; it < 4; it++) {
            int b = it * 256 + tid;
            int k0 = (b >> 5) * 4, n0 = (b & 31) * 4;
            float4 rr[4];
#pragma unroll
            for (int i = 0; i < 4; i++)
                rr[i] = *(const float4*)&W[(size_t)(kt + k0 + i) * ldw + nBase + n0];
            const float* rf = (const float*)rr;   // rf[i*4+j] = W[kt+k0+i][nBase+n0+j]
#pragma unroll
            for (int j = 0; j < 4; j++) {
                uint32_t l0, l1;
                uint32_t h0 = pack_split(rf[0 * 4 + j], rf[1 * 4 + j], l0);
                uint32_t h1 = pack_split(rf[2 * 4 + j], rf[3 * 4 + j], l1);
                int ho = (n0 + j) * SLDA + k0;
                *(uint2*)(dsm + 2 * (BHI_H + ho)) = make_uint2(h0, h1);
                *(uint2*)(dsm + 2 * (BLO_H + ho)) = make_uint2(l0, l1);
            }
        }
        __syncthreads();

#pragma unroll
        for (int ks = 0; ks < 8; ks++) {
            uint32_t ah[4][4], al[4][4];
#pragma unroll
            for (int mi = 0; mi < 4; mi++) {
                uint32_t addr = sb + 2u * (uint32_t)((wm * 64 + mi * 16 + lrA) * SLDA + ks * 16 + lcA);
                ldsm_x4(ah[mi][0], ah[mi][1], ah[mi][2], ah[mi][3], addr);
                ldsm_x4(al[mi][0], al[mi][1], al[mi][2], al[mi][3], addr + 2u * (uint32_t)ALO_H);
            }
#pragma unroll
            for (int ni = 0; ni < 4; ni++) {
                uint32_t baddr = sb + 2u * (uint32_t)(BHI_H + (wn * 32 + ni * 8 + lrB) * SLDA + ks * 16 + lcB);
                uint32_t bh0, bh1, bl0, bl1;
                ldsm_x2(bh0, bh1, baddr);
                ldsm_x2(bl0, bl1, baddr + 2u * (uint32_t)(BLO_H - BHI_H));
#pragma unroll
                for (int mi = 0; mi < 4; mi++) {
                    mma_bf16(c[mi][ni], ah[mi][0], ah[mi][1], ah[mi][2], ah[mi][3], bh0, bh1);
                    mma_bf16(c[mi][ni], al[mi][0], al[mi][1], al[mi][2], al[mi][3], bh0, bh1);
                    mma_bf16(c[mi][ni], ah[mi][0], ah[mi][1], ah[mi][2], ah[mi][3], bl0, bl1);
                }
            }
        }
        __syncthreads();
    }

    // ---- epilogue ----
    const int gq = lane >> 2;
    const int c2 = (lane & 3) * 2;
#pragma unroll
    for (int mi = 0; mi < 4; mi++) {
#pragma unroll
        for (int ni = 0; ni < 4; ni++) {
            int colg = nBase + wn * 32 + ni * 8 + c2;
            float2 bb = *(const float2*)&bias[colg];
#pragma unroll
            for (int half = 0; half < 2; half++) {
                int gr = rowBase + wm * 64 + mi * 16 + gq + half * 8;
                if (gr >= M) continue;
                float v0 = c[mi][ni][half * 2 + 0] + bb.x;
                float v1 = c[mi][ni][half * 2 + 1] + bb.y;
                if (mode == 0) {
                    *(float2*)&C[(size_t)gr * ldc + colg] = make_float2(v0, v1);
                } else if (mode == 1) {
                    *(float2*)&C[(size_t)gr * ldc + colg] = make_float2(geluf(v0), geluf(v1));
                } else if (mode == 2) {
                    float2 r4 = *(const float2*)&extra[(size_t)gr * 128 + colg];
                    *(float2*)&C[(size_t)gr * ldc + colg] = make_float2(v0 + r4.x, v1 + r4.y);
                } else {
                    float2 xl = *(const float2*)&C[(size_t)gr * ldc + colg];
                    float2 xr = *(const float2*)&extra[(size_t)gr * 128 + colg];
                    *(float2*)&C[(size_t)gr * ldc + 128 + colg] = make_float2(xl.x + v0, xl.y + v1);
                    *(float2*)&C[(size_t)gr * ldc + 256 + colg] = make_float2(xr.x - v0, xr.y - v1);
                }
            }
        }
    }
}

// ---------------- edge pass 1: logits + segment max (warp per edge) ----------------
__global__ void __launch_bounds__(256) k_logits(const int* __restrict__ ei,
                                                const float* __restrict__ pos,
                                                const float* __restrict__ We,
                                                const float* __restrict__ att, int E, int M) {
    int e = blockIdx.x * 8 + (threadIdx.x >> 5);
    if (e >= E) return;
    int l = threadIdx.x & 31;
    int is64 = g_is64;
    int s = eidx(ei, (size_t)e, is64, M);
    int d = eidx(ei, (size_t)E + e, is64, M);
    float2 ps = ((const float2*)pos)[s];
    float2 pd = ((const float2*)pos)[d];
    float rx = ps.x - pd.x, ry = ps.y - pd.y;
    float dsq = rx * rx + ry * ry + 1e-8f;
    float ox = -ry / dsq;
    float oy =  rx / dsq;
    float4 a4 = *(const float4*)(g_scratch + OFF_P + (size_t)s * 384 + 128 + 4 * l);
    float4 b4 = *(const float4*)(g_scratch + OFF_P + (size_t)d * 384 + 256 + 4 * l);
    float4 c0 = *(const float4*)(We + 128 * 128 + 4 * l);
    float4 c1 = *(const float4*)(We + 129 * 128 + 4 * l);
    float4 x;
    x.x = a4.x + b4.x + ox * c0.x + oy * c1.x;
    x.y = a4.y + b4.y + ox * c0.y + oy * c1.y;
    x.z = a4.z + b4.z + ox * c0.z + oy * c1.z;
    x.w = a4.w + b4.w + ox * c0.w + oy * c1.w;
    x.x = x.x > 0.f ? x.x : 0.2f * x.x;
    x.y = x.y > 0.f ? x.y : 0.2f * x.y;
    x.z = x.z > 0.f ? x.z : 0.2f * x.z;
    x.w = x.w > 0.f ? x.w : 0.2f * x.w;
    float4 at = *(const float4*)(att + 4 * l);
    float p = x.x * at.x + x.y * at.y + x.z * at.z + x.w * at.w;
    p += __shfl_xor_sync(0xffffffffu, p, 4);
    p += __shfl_xor_sync(0xffffffffu, p, 2);
    p += __shfl_xor_sync(0xffffffffu, p, 1);
    if ((l & 7) == 0) {
        int h = l >> 3;
        g_scratch[OFF_LOGIT + (size_t)e * 4 + h] = p;
        atomicMaxF(&g_scratch[OFF_AMAX + (size_t)d * 4 + h], p);
    }
}

// ---------------- edge pass 2: exp + unnormalized scatter (warp per edge, v4 RED) ----------------
__global__ void __launch_bounds__(256) k_scat(const int* __restrict__ ei, int E, int M) {
    int e = blockIdx.x * 8 + (threadIdx.x >> 5);
    if (e >= E) return;
    int l = threadIdx.x & 31;
    int is64 = g_is64;
    int s = eidx(ei, (size_t)e, is64, M);
    int d = eidx(ei, (size_t)E + e, is64, M);
    float4 lg = *(const float4*)&g_scratch[OFF_LOGIT + (size_t)e * 4];
    float4 am = *(const float4*)&g_scratch[OFF_AMAX + (size_t)d * 4];
    int h = l >> 3;
    float lgh = (h < 2) ? (h == 0 ? lg.x : lg.y) : (h == 2 ? lg.z : lg.w);
    float amh = (h < 2) ? (h == 0 ? am.x : am.y) : (h == 2 ? am.z : am.w);
    float eh = expf(lgh - amh);
    float e0 = __shfl_sync(0xffffffffu, eh, 0);
    float e1 = __shfl_sync(0xffffffffu, eh, 8);
    float e2 = __shfl_sync(0xffffffffu, eh, 16);
    float e3 = __shfl_sync(0xffffffffu, eh, 24);
    if (l == 0)
        atomicAdd((float4*)&g_scratch[OFF_DENOM + (size_t)d * 4], make_float4(e0, e1, e2, e3));
    float4 xl = *(const float4*)(g_scratch + OFF_P + (size_t)s * 384 + 4 * l);
    atomicAdd((float4*)(g_scratch + OFF_AGGR + (size_t)d * 128 + 4 * l),
              make_float4(xl.x * eh, xl.y * eh, xl.z * eh, xl.w * eh));
}

// ---------------- normalize aggregated messages per (node, head) ----------------
__global__ void __launch_bounds__(256) k_norm(int M) {
    int n = blockIdx.x * 8 + (threadIdx.x >> 5);
    if (n >= M) return;
    int l = threadIdx.x & 31;
    int h = l >> 3;
    float dn = g_scratch[OFF_DENOM + (size_t)n * 4 + h];
    float r = 1.f / (dn + 1e-16f);
    float4* p = (float4*)(g_scratch + OFF_AGGR + (size_t)n * 128) + l;
    float4 v = *p;
    v.x *= r; v.y *= r; v.z *= r; v.w *= r;
    *p = v;
}

// ---------------- LayerNorm (warp per node) ----------------
__global__ void __launch_bounds__(256) k_ln(const float* __restrict__ lnw,
                                            const float* __restrict__ lnb, int M) {
    int n = blockIdx.x * 8 + (threadIdx.x >> 5);
    if (n >= M) return;
    int l = threadIdx.x & 31;
    float4 v = ((const float4*)(g_scratch + OFF_AGGR2 + (size_t)n * 128))[l];
    float s = v.x + v.y + v.z + v.w;
    float q = v.x * v.x + v.y * v.y + v.z * v.z + v.w * v.w;
#pragma unroll
    for (int o = 16; o; o >>= 1) {
        s += __shfl_xor_sync(0xffffffffu, s, o);
        q += __shfl_xor_sync(0xffffffffu, q, o);
    }
    float mean = s * (1.f / 128.f);
    float var  = q * (1.f / 128.f) - mean * mean;
    float rstd = rsqrtf(var + 1e-5f);
    float4 w = ((const float4*)lnw)[l];
    float4 b = ((const float4*)lnb)[l];
    float4 o4;
    o4.x = (v.x - mean) * rstd * w.x + b.x;
    o4.y = (v.y - mean) * rstd * w.y + b.y;
    o4.z = (v.z - mean) * rstd * w.z + b.z;
    o4.w = (v.w - mean) * rstd * w.w + b.w;
    ((float4*)(g_scratch + OFF_HMOD + (size_t)n * 128))[l] = o4;
}

// ---------------- launch ----------------
extern "C" void kernel_launch(void* const* d_in, const int* in_sizes, int n_in,
                              void* d_out, int out_size) {
    const float* h_target = (const float*)d_in[0];
    const float* h_source = (const float*)d_in[1];
    const int* ei      = (const int*)d_in[2];
    const float* pos   = (const float*)d_in[3];
    const float* t_emb = (const float*)d_in[4];
    const float* gn_w  = (const float*)d_in[5];
    const float* gn_b  = (const float*)d_in[6];
    const float* fcW   = (const float*)d_in[7];
    const float* fcb   = (const float*)d_in[8];
    const float* Wl    = (const float*)d_in[9];
    const float* bl    = (const float*)d_in[10];
    const float* Wr    = (const float*)d_in[11];
    const float* br    = (const float*)d_in[12];
    const float* We    = (const float*)d_in[13];
    const float* att   = (const float*)d_in[14];
    const float* gatb  = (const float*)d_in[15];
    const float* Wp    = (const float*)d_in[16];
    const float* bp    = (const float*)d_in[17];
    const float* lnw   = (const float*)d_in[18];
    const float* lnb   = (const float*)d_in[19];
    const float* W1    = (const float*)d_in[20];
    const float* b1    = (const float*)d_in[21];
    const float* W2    = (const float*)d_in[22];
    const float* b2    = (const float*)d_in[23];

    int M = in_sizes[0] / 128; if (M > NN) M = NN;
    int E = in_sizes[2] / 2;   if (E > EE) E = EE;

    float* sc = nullptr;
    cudaGetSymbolAddress((void**)&sc, g_scratch);
    float* P     = sc + OFF_P;
    float* HM    = sc + OFF_HMOD;
    float* AGGR  = sc + OFF_AGGR;
    float* AGGR2 = sc + OFF_AGGR2;
    float* BIAS2 = sc + OFF_BIAS2;
    float* ZERO  = sc + OFF_ZERO;

    cudaFuncSetAttribute(k_mma, cudaFuncAttributeMaxDynamicSharedMemorySize, SMEM_BYTES);

    dim3 blk(256);
    dim3 g1((M + 127) / 128, 1);
    dim3 g2((M + 127) / 128, 2);

    k_detect<<<1, 1>>>(ei);
    k_style<<<1, 384>>>(t_emb, fcW, fcb, gatb, Wp, bp);
    k_init<<<2048, 256>>>();
    k_adagn<<<(M + 1) / 2, 256>>>(h_source, gn_w, gn_b, M);

    // node transforms: x_l -> P+0 ; x_r -> AGGR2 (temp) ; hWe fused-combine -> P+128 / P+256
    k_mma<<<g1, blk, SMEM_BYTES>>>(HM, 128, Wl, 128, bl,   P,     384, M, 128, 0, nullptr);
    k_mma<<<g1, blk, SMEM_BYTES>>>(HM, 128, Wr, 128, br,   AGGR2, 128, M, 128, 0, nullptr);
    k_mma<<<g1, blk, SMEM_BYTES>>>(HM, 128, We, 128, ZERO, P,     384, M, 128, 3, AGGR2);

    k_logits<<<(E + 7) / 8, 256>>>(ei, pos, We, att, E, M);
    k_scat<<<(E + 7) / 8, 256>>>(ei, E, M);
    k_norm<<<(M + 7) / 8, 256>>>(M);

    // post_gat: aggr@Wp + (gat_b@Wp + bp)
    k_mma<<<g1, blk, SMEM_BYTES>>>(AGGR, 128, Wp, 128, BIAS2, AGGR2, 128, M, 128, 0, nullptr);
    k_ln<<<(M + 7) / 8, 256>>>(lnw, lnb, M);
    // update MLP: GELU(LN@W1+b1)@W2+b2 + h_target
    k_mma<<<g2, blk, SMEM_BYTES>>>(HM, 128, W1, 256, b1, P, 256, M, 128, 1, nullptr);
    k_mma<<<g1, blk, SMEM_BYTES>>>(P, 256, W2, 128, b2, (float*)d_out, 128, M, 256, 2, h_target);
}

// round 13
// speedup vs baseline: 1.8300x; 1.1183x over previous
#include <cuda_runtime.h>
#include <cuda_bf16.h>
#include <cstdint>
#include <cstddef>

#define NN 50000
#define EE 800000

// ---------------- scratch layout (floats) ----------------
// P region (N*384 floats), time-multiplexed:
//   edge phase: rows of 384: [x_l | A | B] fp32 (stride 384)
//   post-edge:  [0..N*64)      aggr bf16 hi (uint32)
//               [N*64..N*128)  aggr bf16 lo
//               [N*128..N*256) z1 bf16 hi (256 cols -> 128 uint32/row)
//               [N*256..N*384) z1 bf16 lo
// HMOD region (N*128 floats): bf16 staging [0..N*64) hi, [N*64..N*128) lo
//   (first HM from AdaGN, later LN output)
constexpr size_t OFF_P     = 0;
constexpr size_t OFF_HMOD  = OFF_P     + (size_t)NN * 384;
constexpr size_t OFF_LOGIT = OFF_HMOD  + (size_t)NN * 128;   // E*4 logits
constexpr size_t OFF_AMAX  = OFF_LOGIT + (size_t)EE * 4;     // N*4
constexpr size_t OFF_DENOM = OFF_AMAX  + (size_t)NN * 4;     // N*4
constexpr size_t OFF_AGGR  = OFF_DENOM + (size_t)NN * 4;     // N*128 fp32 atomic accum
constexpr size_t OFF_AGGR2 = OFF_AGGR  + (size_t)NN * 128;   // N*128 (x_r temp, then Wp out fp32)
constexpr size_t OFF_STYLE = OFF_AGGR2 + (size_t)NN * 128;   // 256
constexpr size_t OFF_BIAS2 = OFF_STYLE + 256;                // 128
constexpr size_t OFF_ZERO  = OFF_BIAS2 + 128;                // 128 zeros
constexpr size_t OFF_WSTG  = OFF_ZERO + 128;                 // 131072 uint32 staged weights
constexpr size_t SCRATCH_TOTAL = OFF_WSTG + 131072;

// staged weight offsets (uint32 units within WSTG)
constexpr int WS_WL = 0;        // 128x128: hi 8192 | lo 8192
constexpr int WS_WR = 16384;
constexpr int WS_WE = 32768;
constexpr int WS_WP = 49152;
constexpr int WS_W1 = 65536;    // 256x128: hi 16384 | lo 16384
constexpr int WS_W2 = 98304;    // 128x256: hi 16384 | lo 16384

__device__ __align__(16) float g_scratch[SCRATCH_TOTAL];
__device__ int g_is64;

// ---------------- helpers ----------------
__device__ __forceinline__ float geluf(float x) {
    return 0.5f * x * (1.f + erff(x * 0.70710678118654752440f));
}
__device__ __forceinline__ void atomicMaxF(float* addr, float v) {
    if (v >= 0.f) atomicMax((int*)addr, __float_as_int(v));
    else          atomicMin((unsigned int*)addr, __float_as_uint(v));
}
__device__ __forceinline__ int eidx(const int* __restrict__ ei32, size_t pos, int is64, int M) {
    int v = ei32[is64 ? (pos << 1) : pos];
    if ((unsigned)v >= (unsigned)M) v = 0;
    return v;
}
__device__ __forceinline__ uint32_t s2u(const void* p) {
    uint32_t a;
    asm("{ .reg .u64 t; cvta.to.shared.u64 t, %1; cvt.u32.u64 %0, t; }" : "=r"(a) : "l"(p));
    return a;
}
__device__ __forceinline__ void ldsm_x4(uint32_t& r0, uint32_t& r1, uint32_t& r2, uint32_t& r3, uint32_t addr) {
    asm volatile("ldmatrix.sync.aligned.m8n8.x4.shared.b16 {%0,%1,%2,%3}, [%4];"
                 : "=r"(r0), "=r"(r1), "=r"(r2), "=r"(r3) : "r"(addr));
}
__device__ __forceinline__ void ldsm_x2(uint32_t& r0, uint32_t& r1, uint32_t addr) {
    asm volatile("ldmatrix.sync.aligned.m8n8.x2.shared.b16 {%0,%1}, [%2];"
                 : "=r"(r0), "=r"(r1) : "r"(addr));
}
__device__ __forceinline__ void mma_bf16(float* c, uint32_t a0, uint32_t a1, uint32_t a2, uint32_t a3,
                                         uint32_t b0, uint32_t b1) {
    asm volatile("mma.sync.aligned.m16n8k16.row.col.f32.bf16.bf16.f32 "
                 "{%0,%1,%2,%3}, {%4,%5,%6,%7}, {%8,%9}, {%0,%1,%2,%3};"
                 : "+f"(c[0]), "+f"(c[1]), "+f"(c[2]), "+f"(c[3])
                 : "r"(a0), "r"(a1), "r"(a2), "r"(a3), "r"(b0), "r"(b1));
}
__device__ __forceinline__ uint32_t pack_split(float a, float b, uint32_t& lo) {
    __nv_bfloat16 ha = __float2bfloat16(a), hb = __float2bfloat16(b);
    float ra = a - __bfloat162float(ha), rb = b - __bfloat162float(hb);
    __nv_bfloat16 la = __float2bfloat16(ra), lb = __float2bfloat16(rb);
    unsigned short uha = *(unsigned short*)&ha, uhb = *(unsigned short*)&hb;
    unsigned short ula = *(unsigned short*)&la, ulb = *(unsigned short*)&lb;
    lo = (uint32_t)ula | ((uint32_t)ulb << 16);
    return (uint32_t)uha | ((uint32_t)uhb << 16);
}

// ---------------- detect edge_index dtype ----------------
__global__ void k_detect(const int* __restrict__ ei32) {
    int z = 0;
#pragma unroll
    for (int i = 0; i < 16; i++) z |= ei32[2 * i + 1];
    g_is64 = (z == 0) ? 1 : 0;
}

// ---------------- weight convert: staged[n][k/2] = pack(W[2kp][n], W[2kp+1][n]) ----------------
__global__ void k_wconv(const float* __restrict__ W, int kdim, int ndim, int dstOff) {
    int t = blockIdx.x * 256 + threadIdx.x;
    int kh = kdim >> 1;
    int tot = ndim * kh;
    if (t >= tot) return;
    int n = t / kh, kp = t % kh;
    float a = W[(size_t)(2 * kp) * ndim + n];
    float b = W[(size_t)(2 * kp + 1) * ndim + n];
    uint32_t l, h = pack_split(a, b, l);
    uint32_t* ws = (uint32_t*)(g_scratch + OFF_WSTG) + dstOff;
    ws[(size_t)n * kh + kp] = h;
    ws[(size_t)tot + (size_t)n * kh + kp] = l;
}

// ---------------- tiny precompute ----------------
__global__ void k_style(const float* __restrict__ t_emb, const float* __restrict__ fcW,
                        const float* __restrict__ fcb, const float* __restrict__ gatb,
                        const float* __restrict__ Wp, const float* __restrict__ bp) {
    int j = threadIdx.x;
    if (j < 256) {
        float s = fcb[j];
        for (int i = 0; i < 128; i++) s += t_emb[i] * fcW[i * 256 + j];
        g_scratch[OFF_STYLE + j] = s;
    } else if (j < 384) {
        int c = j - 256;
        float s = bp[c];
        for (int i = 0; i < 128; i++) s += gatb[i] * Wp[i * 128 + c];
        g_scratch[OFF_BIAS2 + c] = s;
    }
}

// ---------------- init accumulators ----------------
__global__ void k_init() {
    size_t stride = (size_t)gridDim.x * blockDim.x;
    size_t t0 = (size_t)blockIdx.x * blockDim.x + threadIdx.x;
    for (size_t i = t0; i < (size_t)NN * 128; i += stride)
        g_scratch[OFF_AGGR + i] = 0.f;
    for (size_t i = t0; i < (size_t)NN * 4; i += stride) {
        g_scratch[OFF_AMAX + i]  = -1e30f;
        g_scratch[OFF_DENOM + i] = 0.f;
    }
}

// ---------------- AdaGN -> packed bf16 hi/lo ----------------
__global__ void __launch_bounds__(256) k_adagn(const float* __restrict__ hs,
                                               const float* __restrict__ gnw,
                                               const float* __restrict__ gnb, int M) {
    int n = blockIdx.x * 2 + (threadIdx.x >> 7);
    if (n >= M) return;
    int c = threadIdx.x & 127;
    float v = hs[(size_t)n * 128 + c];
    float s = v, q = v * v;
#pragma unroll
    for (int o = 8; o; o >>= 1) {
        s += __shfl_xor_sync(0xffffffffu, s, o, 16);
        q += __shfl_xor_sync(0xffffffffu, q, o, 16);
    }
    float mean = s * (1.f / 16.f);
    float var  = q * (1.f / 16.f) - mean * mean;
    float nv   = (v - mean) * rsqrtf(var + 1e-5f);
    float hm   = (nv * gnw[c] + gnb[c]) * (1.f + g_scratch[OFF_STYLE + c]) + g_scratch[OFF_STYLE + 128 + c];
    float hm2  = __shfl_down_sync(0xffffffffu, hm, 1);
    if (!(c & 1)) {
        uint32_t l, h = pack_split(hm, hm2, l);
        uint32_t* st = (uint32_t*)(g_scratch + OFF_HMOD);
        st[(size_t)n * 64 + (c >> 1)] = h;
        st[(size_t)NN * 64 + (size_t)n * 64 + (c >> 1)] = l;
    }
}

// ======================================================================
// HMMA bf16 3-term split GEMM core (packed bf16 hi/lo inputs)
// ======================================================================
constexpr int SLDA  = 136;                 // halves per smem row
constexpr int TILEH = 128 * SLDA;
constexpr int AHI_H = 0;
constexpr int ALO_H = TILEH;
constexpr int BHI_H = 2 * TILEH;
constexpr int BLO_H = 3 * TILEH;
constexpr int SMEM_BYTES = 4 * TILEH * 2;  // 139264

// load one 128x(128 bf16) packed tile into smem half-region
__device__ __forceinline__ void ld_tile(char* dsm, int half_base, const uint32_t* __restrict__ src,
                                        int ld32, int k32off, int rowBase, int rowMax, int tid) {
#pragma unroll
    for (int it = 0; it < 8; it++) {
        int idx = it * 256 + tid;
        int row = idx >> 4, c16 = idx & 15;
        int gr = rowBase + row;
        if (gr > rowMax) gr = rowMax;
        uint4 v = *(const uint4*)(src + (size_t)gr * ld32 + k32off + c16 * 4);
        *(uint4*)(dsm + 2 * (half_base + row * SLDA) + c16 * 16) = v;
    }
}

__device__ __forceinline__ void mma_chunk(uint32_t sb, int wm, int wn, int lane, float c[4][4][4]) {
    const int lrA = lane & 15, lcA = (lane >> 4) << 3;
    const int lrB = lane & 7,  lcB = ((lane >> 3) & 1) << 3;
#pragma unroll
    for (int ks = 0; ks < 8; ks++) {
        uint32_t ah[4][4], al[4][4];
#pragma unroll
        for (int mi = 0; mi < 4; mi++) {
            uint32_t addr = sb + 2u * (uint32_t)((wm * 64 + mi * 16 + lrA) * SLDA + ks * 16 + lcA);
            ldsm_x4(ah[mi][0], ah[mi][1], ah[mi][2], ah[mi][3], addr);
            ldsm_x4(al[mi][0], al[mi][1], al[mi][2], al[mi][3], addr + 2u * (uint32_t)ALO_H);
        }
#pragma unroll
        for (int ni = 0; ni < 4; ni++) {
            uint32_t baddr = sb + 2u * (uint32_t)(BHI_H + (wn * 32 + ni * 8 + lrB) * SLDA + ks * 16 + lcB);
            uint32_t bh0, bh1, bl0, bl1;
            ldsm_x2(bh0, bh1, baddr);
            ldsm_x2(bl0, bl1, baddr + 2u * (uint32_t)(BLO_H - BHI_H));
#pragma unroll
            for (int mi = 0; mi < 4; mi++) {
                mma_bf16(c[mi][ni], ah[mi][0], ah[mi][1], ah[mi][2], ah[mi][3], bh0, bh1);
                mma_bf16(c[mi][ni], al[mi][0], al[mi][1], al[mi][2], al[mi][3], bh0, bh1);
                mma_bf16(c[mi][ni], ah[mi][0], ah[mi][1], ah[mi][2], ah[mi][3], bl0, bl1);
            }
        }
    }
}

// generic GEMM: modes 0 plain fp32, 1 GELU->packed bf16, 2 fp32 + extra residual
__global__ void __launch_bounds__(256, 1) k_mma(
    const uint32_t* __restrict__ Ahi, const uint32_t* __restrict__ Alo, int lda32,
    const uint32_t* __restrict__ Bhi, const uint32_t* __restrict__ Blo, int ldb32,
    const float* __restrict__ bias, int mode,
    float* __restrict__ Cf, int ldc, const float* __restrict__ extra,
    uint32_t* __restrict__ Cohi, uint32_t* __restrict__ Colo, int ldco,
    int M, int K)
{
    extern __shared__ __align__(16) char dsm[];
    const int tid = threadIdx.x;
    const int w = tid >> 5, lane = tid & 31;
    const uint32_t sb = s2u(dsm);
    const int rowBase = blockIdx.x * 128;
    const int nBase = blockIdx.y * 128;
    const int wm = w & 1, wn = w >> 1;

    const uint32_t* bh = Bhi + (size_t)nBase * ldb32;
    const uint32_t* bl = Blo + (size_t)nBase * ldb32;

    float c[4][4][4];
#pragma unroll
    for (int i = 0; i < 4; i++)
#pragma unroll
        for (int j = 0; j < 4; j++)
#pragma unroll
            for (int q = 0; q < 4; q++) c[i][j][q] = 0.f;

    for (int kt = 0; kt < K; kt += 128) {
        int k32 = kt >> 1;
        ld_tile(dsm, AHI_H, Ahi, lda32, k32, rowBase, M - 1, tid);
        ld_tile(dsm, ALO_H, Alo, lda32, k32, rowBase, M - 1, tid);
        ld_tile(dsm, BHI_H, bh, ldb32, k32, 0, 127, tid);
        ld_tile(dsm, BLO_H, bl, ldb32, k32, 0, 127, tid);
        __syncthreads();
        mma_chunk(sb, wm, wn, lane, c);
        __syncthreads();
    }

    const int gq = lane >> 2;
    const int c2 = (lane & 3) * 2;
#pragma unroll
    for (int mi = 0; mi < 4; mi++) {
#pragma unroll
        for (int ni = 0; ni < 4; ni++) {
            int colg = nBase + wn * 32 + ni * 8 + c2;
            float2 bb = *(const float2*)&bias[colg];
#pragma unroll
            for (int half = 0; half < 2; half++) {
                int gr = rowBase + wm * 64 + mi * 16 + gq + half * 8;
                if (gr >= M) continue;
                float v0 = c[mi][ni][half * 2 + 0] + bb.x;
                float v1 = c[mi][ni][half * 2 + 1] + bb.y;
                if (mode == 0) {
                    *(float2*)&Cf[(size_t)gr * ldc + colg] = make_float2(v0, v1);
                } else if (mode == 1) {
                    uint32_t l, h = pack_split(geluf(v0), geluf(v1), l);
                    Cohi[(size_t)gr * ldco + (colg >> 1)] = h;
                    Colo[(size_t)gr * ldco + (colg >> 1)] = l;
                } else {
                    float2 r4 = *(const float2*)&extra[(size_t)gr * 128 + colg];
                    *(float2*)&Cf[(size_t)gr * ldc + colg] = make_float2(v0 + r4.x, v1 + r4.y);
                }
            }
        }
    }
}

// fused node-transform GEMM: A (HM bf16) loaded once, loop over Wl/Wr/We
__global__ void __launch_bounds__(256, 1) k_mma3(
    const uint32_t* __restrict__ Ahi, const uint32_t* __restrict__ Alo,
    const float* __restrict__ bl_, const float* __restrict__ br_,
    float* __restrict__ P, float* __restrict__ XR, int M)
{
    extern __shared__ __align__(16) char dsm[];
    const int tid = threadIdx.x;
    const int w = tid >> 5, lane = tid & 31;
    const uint32_t sb = s2u(dsm);
    const int rowBase = blockIdx.x * 128;
    const int wm = w & 1, wn = w >> 1;
    const uint32_t* ws = (const uint32_t*)(g_scratch + OFF_WSTG);
    const int wsoff[3] = {WS_WL, WS_WR, WS_WE};

    ld_tile(dsm, AHI_H, Ahi, 64, 0, rowBase, M - 1, tid);
    ld_tile(dsm, ALO_H, Alo, 64, 0, rowBase, M - 1, tid);
    ld_tile(dsm, BHI_H, ws + wsoff[0], 64, 0, 0, 127, tid);
    ld_tile(dsm, BLO_H, ws + wsoff[0] + 8192, 64, 0, 0, 127, tid);
    __syncthreads();

    const int gq = lane >> 2;
    const int c2 = (lane & 3) * 2;

#pragma unroll
    for (int t = 0; t < 3; t++) {
        float c[4][4][4];
#pragma unroll
        for (int i = 0; i < 4; i++)
#pragma unroll
            for (int j = 0; j < 4; j++)
#pragma unroll
                for (int q = 0; q < 4; q++) c[i][j][q] = 0.f;

        mma_chunk(sb, wm, wn, lane, c);

        // epilogue t
#pragma unroll
        for (int mi = 0; mi < 4; mi++) {
#pragma unroll
            for (int ni = 0; ni < 4; ni++) {
                int colg = wn * 32 + ni * 8 + c2;
                float2 bb = make_float2(0.f, 0.f);
                if (t == 0) bb = *(const float2*)&bl_[colg];
                else if (t == 1) bb = *(const float2*)&br_[colg];
#pragma unroll
                for (int half = 0; half < 2; half++) {
                    int gr = rowBase + wm * 64 + mi * 16 + gq + half * 8;
                    if (gr >= M) continue;
                    float v0 = c[mi][ni][half * 2 + 0] + bb.x;
                    float v1 = c[mi][ni][half * 2 + 1] + bb.y;
                    if (t == 0) {
                        *(float2*)&P[(size_t)gr * 384 + colg] = make_float2(v0, v1);
                    } else if (t == 1) {
                        *(float2*)&XR[(size_t)gr * 128 + colg] = make_float2(v0, v1);
                    } else {
                        float2 xl = *(const float2*)&P[(size_t)gr * 384 + colg];
                        float2 xr = *(const float2*)&XR[(size_t)gr * 128 + colg];
                        *(float2*)&P[(size_t)gr * 384 + 128 + colg] = make_float2(xl.x + v0, xl.y + v1);
                        *(float2*)&P[(size_t)gr * 384 + 256 + colg] = make_float2(xr.x - v0, xr.y - v1);
                    }
                }
            }
        }
        __syncthreads();
        if (t < 2) {
            ld_tile(dsm, BHI_H, ws + wsoff[t + 1], 64, 0, 0, 127, tid);
            ld_tile(dsm, BLO_H, ws + wsoff[t + 1] + 8192, 64, 0, 0, 127, tid);
            __syncthreads();
        }
    }
}

// ---------------- edge pass 1: logits + segment max (warp per edge) ----------------
__global__ void __launch_bounds__(256) k_logits(const int* __restrict__ ei,
                                                const float* __restrict__ pos,
                                                const float* __restrict__ We,
                                                const float* __restrict__ att, int E, int M) {
    int e = blockIdx.x * 8 + (threadIdx.x >> 5);
    if (e >= E) return;
    int l = threadIdx.x & 31;
    int is64 = g_is64;
    int s = eidx(ei, (size_t)e, is64, M);
    int d = eidx(ei, (size_t)E + e, is64, M);
    float2 ps = ((const float2*)pos)[s];
    float2 pd = ((const float2*)pos)[d];
    float rx = ps.x - pd.x, ry = ps.y - pd.y;
    float dsq = rx * rx + ry * ry + 1e-8f;
    float ox = -ry / dsq;
    float oy =  rx / dsq;
    float4 a4 = *(const float4*)(g_scratch + OFF_P + (size_t)s * 384 + 128 + 4 * l);
    float4 b4 = *(const float4*)(g_scratch + OFF_P + (size_t)d * 384 + 256 + 4 * l);
    float4 c0 = *(const float4*)(We + 128 * 128 + 4 * l);
    float4 c1 = *(const float4*)(We + 129 * 128 + 4 * l);
    float4 x;
    x.x = a4.x + b4.x + ox * c0.x + oy * c1.x;
    x.y = a4.y + b4.y + ox * c0.y + oy * c1.y;
    x.z = a4.z + b4.z + ox * c0.z + oy * c1.z;
    x.w = a4.w + b4.w + ox * c0.w + oy * c1.w;
    x.x = x.x > 0.f ? x.x : 0.2f * x.x;
    x.y = x.y > 0.f ? x.y : 0.2f * x.y;
    x.z = x.z > 0.f ? x.z : 0.2f * x.z;
    x.w = x.w > 0.f ? x.w : 0.2f * x.w;
    float4 at = *(const float4*)(att + 4 * l);
    float p = x.x * at.x + x.y * at.y + x.z * at.z + x.w * at.w;
    p += __shfl_xor_sync(0xffffffffu, p, 4);
    p += __shfl_xor_sync(0xffffffffu, p, 2);
    p += __shfl_xor_sync(0xffffffffu, p, 1);
    if ((l & 7) == 0) {
        int h = l >> 3;
        g_scratch[OFF_LOGIT + (size_t)e * 4 + h] = p;
        atomicMaxF(&g_scratch[OFF_AMAX + (size_t)d * 4 + h], p);
    }
}

// ---------------- edge pass 2: exp + unnormalized scatter ----------------
__global__ void __launch_bounds__(256) k_scat(const int* __restrict__ ei, int E, int M) {
    int e = blockIdx.x * 8 + (threadIdx.x >> 5);
    if (e >= E) return;
    int l = threadIdx.x & 31;
    int is64 = g_is64;
    int s = eidx(ei, (size_t)e, is64, M);
    int d = eidx(ei, (size_t)E + e, is64, M);
    float4 lg = *(const float4*)&g_scratch[OFF_LOGIT + (size_t)e * 4];
    float4 am = *(const float4*)&g_scratch[OFF_AMAX + (size_t)d * 4];
    int h = l >> 3;
    float lgh = (h < 2) ? (h == 0 ? lg.x : lg.y) : (h == 2 ? lg.z : lg.w);
    float amh = (h < 2) ? (h == 0 ? am.x : am.y) : (h == 2 ? am.z : am.w);
    float eh = expf(lgh - amh);
    float e0 = __shfl_sync(0xffffffffu, eh, 0);
    float e1 = __shfl_sync(0xffffffffu, eh, 8);
    float e2 = __shfl_sync(0xffffffffu, eh, 16);
    float e3 = __shfl_sync(0xffffffffu, eh, 24);
    if (l == 0)
        atomicAdd((float4*)&g_scratch[OFF_DENOM + (size_t)d * 4], make_float4(e0, e1, e2, e3));
    float4 xl = *(const float4*)(g_scratch + OFF_P + (size_t)s * 384 + 4 * l);
    atomicAdd((float4*)(g_scratch + OFF_AGGR + (size_t)d * 128 + 4 * l),
              make_float4(xl.x * eh, xl.y * eh, xl.z * eh, xl.w * eh));
}

// ---------------- normalize -> packed bf16 hi/lo into P region ----------------
__global__ void __launch_bounds__(256) k_norm(int M) {
    int n = blockIdx.x * 8 + (threadIdx.x >> 5);
    if (n >= M) return;
    int l = threadIdx.x & 31;
    int h = l >> 3;
    float dn = g_scratch[OFF_DENOM + (size_t)n * 4 + h];
    float r = 1.f / (dn + 1e-16f);
    float4 v = ((const float4*)(g_scratch + OFF_AGGR + (size_t)n * 128))[l];
    v.x *= r; v.y *= r; v.z *= r; v.w *= r;
    uint32_t l0, l1;
    uint32_t h0 = pack_split(v.x, v.y, l0);
    uint32_t h1 = pack_split(v.z, v.w, l1);
    uint32_t* HI = (uint32_t*)(g_scratch + OFF_P);
    HI[(size_t)n * 64 + 2 * l]     = h0;
    HI[(size_t)n * 64 + 2 * l + 1] = h1;
    HI[(size_t)NN * 64 + (size_t)n * 64 + 2 * l]     = l0;
    HI[(size_t)NN * 64 + (size_t)n * 64 + 2 * l + 1] = l1;
}

// ---------------- LayerNorm -> packed bf16 hi/lo staging ----------------
__global__ void __launch_bounds__(256) k_ln(const float* __restrict__ lnw,
                                            const float* __restrict__ lnb, int M) {
    int n = blockIdx.x * 8 + (threadIdx.x >> 5);
    if (n >= M) return;
    int l = threadIdx.x & 31;
    float4 v = ((const float4*)(g_scratch + OFF_AGGR2 + (size_t)n * 128))[l];
    float s = v.x + v.y + v.z + v.w;
    float q = v.x * v.x + v.y * v.y + v.z * v.z + v.w * v.w;
#pragma unroll
    for (int o = 16; o; o >>= 1) {
        s += __shfl_xor_sync(0xffffffffu, s, o);
        q += __shfl_xor_sync(0xffffffffu, q, o);
    }
    float mean = s * (1.f / 128.f);
    float var  = q * (1.f / 128.f) - mean * mean;
    float rstd = rsqrtf(var + 1e-5f);
    float4 w = ((const float4*)lnw)[l];
    float4 b = ((const float4*)lnb)[l];
    float4 o4;
    o4.x = (v.x - mean) * rstd * w.x + b.x;
    o4.y = (v.y - mean) * rstd * w.y + b.y;
    o4.z = (v.z - mean) * rstd * w.z + b.z;
    o4.w = (v.w - mean) * rstd * w.w + b.w;
    uint32_t l0, l1;
    uint32_t h0 = pack_split(o4.x, o4.y, l0);
    uint32_t h1 = pack_split(o4.z, o4.w, l1);
    uint32_t* st = (uint32_t*)(g_scratch + OFF_HMOD);
    st[(size_t)n * 64 + 2 * l]     = h0;
    st[(size_t)n * 64 + 2 * l + 1] = h1;
    st[(size_t)NN * 64 + (size_t)n * 64 + 2 * l]     = l0;
    st[(size_t)NN * 64 + (size_t)n * 64 + 2 * l + 1] = l1;
}

// ---------------- launch ----------------
extern "C" void kernel_launch(void* const* d_in, const int* in_sizes, int n_in,
                              void* d_out, int out_size) {
    const float* h_target = (const float*)d_in[0];
    const float* h_source = (const float*)d_in[1];
    const int* ei      = (const int*)d_in[2];
    const float* pos   = (const float*)d_in[3];
    const float* t_emb = (const float*)d_in[4];
    const float* gn_w  = (const float*)d_in[5];
    const float* gn_b  = (const float*)d_in[6];
    const float* fcW   = (const float*)d_in[7];
    const float* fcb   = (const float*)d_in[8];
    const float* Wl    = (const float*)d_in[9];
    const float* bl    = (const float*)d_in[10];
    const float* Wr    = (const float*)d_in[11];
    const float* br    = (const float*)d_in[12];
    const float* We    = (const float*)d_in[13];
    const float* att   = (const float*)d_in[14];
    const float* gatb  = (const float*)d_in[15];
    const float* Wp    = (const float*)d_in[16];
    const float* bp    = (const float*)d_in[17];
    const float* lnw   = (const float*)d_in[18];
    const float* lnb   = (const float*)d_in[19];
    const float* W1    = (const float*)d_in[20];
    const float* b1    = (const float*)d_in[21];
    const float* W2    = (const float*)d_in[22];
    const float* b2    = (const float*)d_in[23];

    int M = in_sizes[0] / 128; if (M > NN) M = NN;
    int E = in_sizes[2] / 2;   if (E > EE) E = EE;

    float* sc = nullptr;
    cudaGetSymbolAddress((void**)&sc, g_scratch);
    float* P     = sc + OFF_P;
    float* AGGR2 = sc + OFF_AGGR2;
    float* BIAS2 = sc + OFF_BIAS2;
    float* ZERO  = sc + OFF_ZERO;
    uint32_t* HMB  = (uint32_t*)(sc + OFF_HMOD);            // hi | lo (+NN*64)
    uint32_t* AGB  = (uint32_t*)(sc + OFF_P);               // aggr bf16 hi | lo
    uint32_t* Z1HI = (uint32_t*)(sc + OFF_P) + (size_t)NN * 128;
    uint32_t* Z1LO = Z1HI + (size_t)NN * 128;
    uint32_t* WS   = (uint32_t*)(sc + OFF_WSTG);

    cudaFuncSetAttribute(k_mma,  cudaFuncAttributeMaxDynamicSharedMemorySize, SMEM_BYTES);
    cudaFuncSetAttribute(k_mma3, cudaFuncAttributeMaxDynamicSharedMemorySize, SMEM_BYTES);

    dim3 blk(256);
    dim3 g1((M + 127) / 128, 1);
    dim3 g2((M + 127) / 128, 2);

    k_detect<<<1, 1>>>(ei);
    k_style<<<1, 384>>>(t_emb, fcW, fcb, gatb, Wp, bp);
    k_init<<<2048, 256>>>();
    // stage weights (transposed, bf16 hi/lo)
    k_wconv<<<32, 256>>>(Wl, 128, 128, WS_WL);
    k_wconv<<<32, 256>>>(Wr, 128, 128, WS_WR);
    k_wconv<<<32, 256>>>(We, 128, 128, WS_WE);   // first 128 rows only (kdim=128)
    k_wconv<<<32, 256>>>(Wp, 128, 128, WS_WP);
    k_wconv<<<64, 256>>>(W1, 128, 256, WS_W1);
    k_wconv<<<64, 256>>>(W2, 256, 128, WS_W2);

    k_adagn<<<(M + 1) / 2, 256>>>(h_source, gn_w, gn_b, M);

    // fused node transforms (A loaded once): x_l->P, x_r->AGGR2, combine->P+128/P+256
    k_mma3<<<g1, blk, SMEM_BYTES>>>(HMB, HMB + (size_t)NN * 64, bl, br, P, AGGR2, M);

    k_logits<<<(E + 7) / 8, 256>>>(ei, pos, We, att, E, M);
    k_scat<<<(E + 7) / 8, 256>>>(ei, E, M);
    k_norm<<<(M + 7) / 8, 256>>>(M);

    // post_gat: aggr(bf16)@Wp + bias2 -> AGGR2 fp32
    k_mma<<<g1, blk, SMEM_BYTES>>>(AGB, AGB + (size_t)NN * 64, 64,
                                   WS + WS_WP, WS + WS_WP + 8192, 64,
                                   BIAS2, 0, AGGR2, 128, nullptr, nullptr, nullptr, 0, M, 128);
    k_ln<<<(M + 7) / 8, 256>>>(lnw, lnb, M);
    // W1 + GELU -> z1 bf16
    k_mma<<<g2, blk, SMEM_BYTES>>>(HMB, HMB + (size_t)NN * 64, 64,
                                   WS + WS_W1, WS + WS_W1 + 16384, 64,
                                   b1, 1, nullptr, 0, nullptr, Z1HI, Z1LO, 128, M, 128);
    // W2 + residual -> d_out
    k_mma<<<g1, blk, SMEM_BYTES>>>(Z1HI, Z1LO, 128,
                                   WS + WS_W2, WS + WS_W2 + 16384, 128,
                                   b2, 2, (float*)d_out, 128, h_target, nullptr, nullptr, 0, M, 256);
}

// round 14
// speedup vs baseline: 1.9807x; 1.0824x over previous
#include <cuda_runtime.h>
#include <cuda_bf16.h>
#include <cstdint>
#include <cstddef>

#define NN 50000
#define EE 800000

// ---------------- scratch layout (floats) ----------------
// P region (N*384): edge phase rows [x_l | A | B] fp32; later z1 bf16 hi/lo
// HMOD region (N*128): bf16 hi/lo staging (HM, then aggr, then LN out)
constexpr size_t OFF_P     = 0;
constexpr size_t OFF_HMOD  = OFF_P     + (size_t)NN * 384;
constexpr size_t OFF_LOGIT = OFF_HMOD  + (size_t)NN * 128;   // E*4 logits (CSR order)
constexpr size_t OFF_AMAX  = OFF_LOGIT + (size_t)EE * 4;     // unused (kept for layout)
constexpr size_t OFF_DENOM = OFF_AMAX  + (size_t)NN * 4;
constexpr size_t OFF_AGGR  = OFF_DENOM + (size_t)NN * 4;     // N*128: CSR int arrays live here
constexpr size_t OFF_AGGR2 = OFF_AGGR  + (size_t)NN * 128;   // N*128 (x_r temp, then Wp out fp32)
constexpr size_t OFF_STYLE = OFF_AGGR2 + (size_t)NN * 128;   // 256
constexpr size_t OFF_BIAS2 = OFF_STYLE + 256;                // 128
constexpr size_t OFF_ZERO  = OFF_BIAS2 + 128;                // 128 zeros
constexpr size_t OFF_WSTG  = OFF_ZERO + 128;                 // 131072 uint32 staged weights
constexpr size_t SCRATCH_TOTAL = OFF_WSTG + 131072;

// staged weight offsets (uint32 units within WSTG)
constexpr int WS_WL = 0;
constexpr int WS_WR = 16384;
constexpr int WS_WE = 32768;
constexpr int WS_WP = 49152;
constexpr int WS_W1 = 65536;
constexpr int WS_W2 = 98304;

__device__ __align__(16) float g_scratch[SCRATCH_TOTAL];
__device__ int g_is64;

// CSR int layout inside OFF_AGGR (int units): list[E] | off[M+1] | cur[M]
__device__ __forceinline__ int* csr_base() { return (int*)(g_scratch + OFF_AGGR); }

// ---------------- helpers ----------------
__device__ __forceinline__ float geluf(float x) {
    return 0.5f * x * (1.f + erff(x * 0.70710678118654752440f));
}
__device__ __forceinline__ int eidx(const int* __restrict__ ei32, size_t pos, int is64, int M) {
    int v = ei32[is64 ? (pos << 1) : pos];
    if ((unsigned)v >= (unsigned)M) v = 0;
    return v;
}
__device__ __forceinline__ uint32_t s2u(const void* p) {
    uint32_t a;
    asm("{ .reg .u64 t; cvta.to.shared.u64 t, %1; cvt.u32.u64 %0, t; }" : "=r"(a) : "l"(p));
    return a;
}
__device__ __forceinline__ void ldsm_x4(uint32_t& r0, uint32_t& r1, uint32_t& r2, uint32_t& r3, uint32_t addr) {
    asm volatile("ldmatrix.sync.aligned.m8n8.x4.shared.b16 {%0,%1,%2,%3}, [%4];"
                 : "=r"(r0), "=r"(r1), "=r"(r2), "=r"(r3) : "r"(addr));
}
__device__ __forceinline__ void ldsm_x2(uint32_t& r0, uint32_t& r1, uint32_t addr) {
    asm volatile("ldmatrix.sync.aligned.m8n8.x2.shared.b16 {%0,%1}, [%2];"
                 : "=r"(r0), "=r"(r1) : "r"(addr));
}
__device__ __forceinline__ void mma_bf16(float* c, uint32_t a0, uint32_t a1, uint32_t a2, uint32_t a3,
                                         uint32_t b0, uint32_t b1) {
    asm volatile("mma.sync.aligned.m16n8k16.row.col.f32.bf16.bf16.f32 "
                 "{%0,%1,%2,%3}, {%4,%5,%6,%7}, {%8,%9}, {%0,%1,%2,%3};"
                 : "+f"(c[0]), "+f"(c[1]), "+f"(c[2]), "+f"(c[3])
                 : "r"(a0), "r"(a1), "r"(a2), "r"(a3), "r"(b0), "r"(b1));
}
__device__ __forceinline__ uint32_t pack_split(float a, float b, uint32_t& lo) {
    __nv_bfloat16 ha = __float2bfloat16(a), hb = __float2bfloat16(b);
    float ra = a - __bfloat162float(ha), rb = b - __bfloat162float(hb);
    __nv_bfloat16 la = __float2bfloat16(ra), lb = __float2bfloat16(rb);
    unsigned short uha = *(unsigned short*)&ha, uhb = *(unsigned short*)&hb;
    unsigned short ula = *(unsigned short*)&la, ulb = *(unsigned short*)&lb;
    lo = (uint32_t)ula | ((uint32_t)ulb << 16);
    return (uint32_t)uha | ((uint32_t)uhb << 16);
}

// ---------------- detect edge_index dtype ----------------
__global__ void k_detect(const int* __restrict__ ei32) {
    int z = 0;
#pragma unroll
    for (int i = 0; i < 16; i++) z |= ei32[2 * i + 1];
    g_is64 = (z == 0) ? 1 : 0;
}

// ---------------- CSR build ----------------
__global__ void k_zdeg(int E, int M) {
    int i = blockIdx.x * 256 + threadIdx.x;
    if (i < M) csr_base()[E + M + 1 + i] = 0;
}
__global__ void k_prep(const int* __restrict__ ei, int E, int M) {
    int e = blockIdx.x * 256 + threadIdx.x;
    if (e >= E) return;
    int d = eidx(ei, (size_t)E + e, g_is64, M);
    atomicAdd(&csr_base()[E + M + 1 + d], 1);
}
__global__ void __launch_bounds__(1024) k_scan(int E, int M) {
    __shared__ int ssum[1024];
    int* IA = csr_base();
    int* off = IA + E;
    int* cur = IA + E + M + 1;
    int t = threadIdx.x;
    int C = (M + 1023) >> 10;
    int lo = t * C, hi = lo + C; if (hi > M) hi = M; if (lo > M) lo = M;
    int s = 0;
    for (int i = lo; i < hi; i++) s += cur[i];
    ssum[t] = s;
    __syncthreads();
    for (int o = 1; o < 1024; o <<= 1) {
        int v = (t >= o) ? ssum[t - o] : 0;
        __syncthreads();
        ssum[t] += v;
        __syncthreads();
    }
    int pre = (t == 0) ? 0 : ssum[t - 1];
    for (int i = lo; i < hi; i++) {
        int d = cur[i];
        off[i] = pre;
        cur[i] = pre;
        pre += d;
    }
    if (t == 1023) off[M] = ssum[1023];
}
__global__ void k_fill(const int* __restrict__ ei, int E, int M) {
    int e = blockIdx.x * 256 + threadIdx.x;
    if (e >= E) return;
    int is64 = g_is64;
    int s = eidx(ei, (size_t)e, is64, M);
    int d = eidx(ei, (size_t)E + e, is64, M);
    int* IA = csr_base();
    int p = atomicAdd(&IA[E + M + 1 + d], 1);
    IA[p] = s;
}

// ---------------- weight convert ----------------
__global__ void k_wconv(const float* __restrict__ W, int kdim, int ndim, int dstOff) {
    int t = blockIdx.x * 256 + threadIdx.x;
    int kh = kdim >> 1;
    int tot = ndim * kh;
    if (t >= tot) return;
    int n = t / kh, kp = t % kh;
    float a = W[(size_t)(2 * kp) * ndim + n];
    float b = W[(size_t)(2 * kp + 1) * ndim + n];
    uint32_t l, h = pack_split(a, b, l);
    uint32_t* ws = (uint32_t*)(g_scratch + OFF_WSTG) + dstOff;
    ws[(size_t)n * kh + kp] = h;
    ws[(size_t)tot + (size_t)n * kh + kp] = l;
}

// ---------------- tiny precompute ----------------
__global__ void k_style(const float* __restrict__ t_emb, const float* __restrict__ fcW,
                        const float* __restrict__ fcb, const float* __restrict__ gatb,
                        const float* __restrict__ Wp, const float* __restrict__ bp) {
    int j = threadIdx.x;
    if (j < 256) {
        float s = fcb[j];
        for (int i = 0; i < 128; i++) s += t_emb[i] * fcW[i * 256 + j];
        g_scratch[OFF_STYLE + j] = s;
    } else if (j < 384) {
        int c = j - 256;
        float s = bp[c];
        for (int i = 0; i < 128; i++) s += gatb[i] * Wp[i * 128 + c];
        g_scratch[OFF_BIAS2 + c] = s;
    }
}

// ---------------- AdaGN -> packed bf16 hi/lo ----------------
__global__ void __launch_bounds__(256) k_adagn(const float* __restrict__ hs,
                                               const float* __restrict__ gnw,
                                               const float* __restrict__ gnb, int M) {
    int n = blockIdx.x * 2 + (threadIdx.x >> 7);
    if (n >= M) return;
    int c = threadIdx.x & 127;
    float v = hs[(size_t)n * 128 + c];
    float s = v, q = v * v;
#pragma unroll
    for (int o = 8; o; o >>= 1) {
        s += __shfl_xor_sync(0xffffffffu, s, o, 16);
        q += __shfl_xor_sync(0xffffffffu, q, o, 16);
    }
    float mean = s * (1.f / 16.f);
    float var  = q * (1.f / 16.f) - mean * mean;
    float nv   = (v - mean) * rsqrtf(var + 1e-5f);
    float hm   = (nv * gnw[c] + gnb[c]) * (1.f + g_scratch[OFF_STYLE + c]) + g_scratch[OFF_STYLE + 128 + c];
    float hm2  = __shfl_down_sync(0xffffffffu, hm, 1);
    if (!(c & 1)) {
        uint32_t l, h = pack_split(hm, hm2, l);
        uint32_t* st = (uint32_t*)(g_scratch + OFF_HMOD);
        st[(size_t)n * 64 + (c >> 1)] = h;
        st[(size_t)NN * 64 + (size_t)n * 64 + (c >> 1)] = l;
    }
}

// ======================================================================
// HMMA bf16 3-term split GEMM core
// ======================================================================
constexpr int SLDA  = 136;
constexpr int TILEH = 128 * SLDA;
constexpr int AHI_H = 0;
constexpr int ALO_H = TILEH;
constexpr int BHI_H = 2 * TILEH;
constexpr int BLO_H = 3 * TILEH;
constexpr int SMEM_BYTES = 4 * TILEH * 2;

__device__ __forceinline__ void ld_tile(char* dsm, int half_base, const uint32_t* __restrict__ src,
                                        int ld32, int k32off, int rowBase, int rowMax, int tid) {
#pragma unroll
    for (int it = 0; it < 8; it++) {
        int idx = it * 256 + tid;
        int row = idx >> 4, c16 = idx & 15;
        int gr = rowBase + row;
        if (gr > rowMax) gr = rowMax;
        uint4 v = *(const uint4*)(src + (size_t)gr * ld32 + k32off + c16 * 4);
        *(uint4*)(dsm + 2 * (half_base + row * SLDA) + c16 * 16) = v;
    }
}

__device__ __forceinline__ void mma_chunk(uint32_t sb, int wm, int wn, int lane, float c[4][4][4]) {
    const int lrA = lane & 15, lcA = (lane >> 4) << 3;
    const int lrB = lane & 7,  lcB = ((lane >> 3) & 1) << 3;
#pragma unroll
    for (int ks = 0; ks < 8; ks++) {
        uint32_t ah[4][4], al[4][4];
#pragma unroll
        for (int mi = 0; mi < 4; mi++) {
            uint32_t addr = sb + 2u * (uint32_t)((wm * 64 + mi * 16 + lrA) * SLDA + ks * 16 + lcA);
            ldsm_x4(ah[mi][0], ah[mi][1], ah[mi][2], ah[mi][3], addr);
            ldsm_x4(al[mi][0], al[mi][1], al[mi][2], al[mi][3], addr + 2u * (uint32_t)ALO_H);
        }
#pragma unroll
        for (int ni = 0; ni < 4; ni++) {
            uint32_t baddr = sb + 2u * (uint32_t)(BHI_H + (wn * 32 + ni * 8 + lrB) * SLDA + ks * 16 + lcB);
            uint32_t bh0, bh1, bl0, bl1;
            ldsm_x2(bh0, bh1, baddr);
            ldsm_x2(bl0, bl1, baddr + 2u * (uint32_t)(BLO_H - BHI_H));
#pragma unroll
            for (int mi = 0; mi < 4; mi++) {
                mma_bf16(c[mi][ni], ah[mi][0], ah[mi][1], ah[mi][2], ah[mi][3], bh0, bh1);
                mma_bf16(c[mi][ni], al[mi][0], al[mi][1], al[mi][2], al[mi][3], bh0, bh1);
                mma_bf16(c[mi][ni], ah[mi][0], ah[mi][1], ah[mi][2], ah[mi][3], bl0, bl1);
            }
        }
    }
}

// generic GEMM: modes 0 plain fp32, 1 GELU->packed bf16, 2 fp32 + extra residual
__global__ void __launch_bounds__(256, 1) k_mma(
    const uint32_t* __restrict__ Ahi, const uint32_t* __restrict__ Alo, int lda32,
    const uint32_t* __restrict__ Bhi, const uint32_t* __restrict__ Blo, int ldb32,
    const float* __restrict__ bias, int mode,
    float* __restrict__ Cf, int ldc, const float* __restrict__ extra,
    uint32_t* __restrict__ Cohi, uint32_t* __restrict__ Colo, int ldco,
    int M, int K)
{
    extern __shared__ __align__(16) char dsm[];
    const int tid = threadIdx.x;
    const int w = tid >> 5, lane = tid & 31;
    const uint32_t sb = s2u(dsm);
    const int rowBase = blockIdx.x * 128;
    const int nBase = blockIdx.y * 128;
    const int wm = w & 1, wn = w >> 1;

    const uint32_t* bh = Bhi + (size_t)nBase * ldb32;
    const uint32_t* bl = Blo + (size_t)nBase * ldb32;

    float c[4][4][4];
#pragma unroll
    for (int i = 0; i < 4; i++)
#pragma unroll
        for (int j = 0; j < 4; j++)
#pragma unroll
            for (int q = 0; q < 4; q++) c[i][j][q] = 0.f;

    for (int kt = 0; kt < K; kt += 128) {
        int k32 = kt >> 1;
        ld_tile(dsm, AHI_H, Ahi, lda32, k32, rowBase, M - 1, tid);
        ld_tile(dsm, ALO_H, Alo, lda32, k32, rowBase, M - 1, tid);
        ld_tile(dsm, BHI_H, bh, ldb32, k32, 0, 127, tid);
        ld_tile(dsm, BLO_H, bl, ldb32, k32, 0, 127, tid);
        __syncthreads();
        mma_chunk(sb, wm, wn, lane, c);
        __syncthreads();
    }

    const int gq = lane >> 2;
    const int c2 = (lane & 3) * 2;
#pragma unroll
    for (int mi = 0; mi < 4; mi++) {
#pragma unroll
        for (int ni = 0; ni < 4; ni++) {
            int colg = nBase + wn * 32 + ni * 8 + c2;
            float2 bb = *(const float2*)&bias[colg];
#pragma unroll
            for (int half = 0; half < 2; half++) {
                int gr = rowBase + wm * 64 + mi * 16 + gq + half * 8;
                if (gr >= M) continue;
                float v0 = c[mi][ni][half * 2 + 0] + bb.x;
                float v1 = c[mi][ni][half * 2 + 1] + bb.y;
                if (mode == 0) {
                    *(float2*)&Cf[(size_t)gr * ldc + colg] = make_float2(v0, v1);
                } else if (mode == 1) {
                    uint32_t l, h = pack_split(geluf(v0), geluf(v1), l);
                    Cohi[(size_t)gr * ldco + (colg >> 1)] = h;
                    Colo[(size_t)gr * ldco + (colg >> 1)] = l;
                } else {
                    float2 r4 = *(const float2*)&extra[(size_t)gr * 128 + colg];
                    *(float2*)&Cf[(size_t)gr * ldc + colg] = make_float2(v0 + r4.x, v1 + r4.y);
                }
            }
        }
    }
}

// fused node-transform GEMM: A (HM bf16) loaded once, loop over Wl/Wr/We
__global__ void __launch_bounds__(256, 1) k_mma3(
    const uint32_t* __restrict__ Ahi, const uint32_t* __restrict__ Alo,
    const float* __restrict__ bl_, const float* __restrict__ br_,
    float* __restrict__ P, float* __restrict__ XR, int M)
{
    extern __shared__ __align__(16) char dsm[];
    const int tid = threadIdx.x;
    const int w = tid >> 5, lane = tid & 31;
    const uint32_t sb = s2u(dsm);
    const int rowBase = blockIdx.x * 128;
    const int wm = w & 1, wn = w >> 1;
    const uint32_t* ws = (const uint32_t*)(g_scratch + OFF_WSTG);
    const int wsoff[3] = {WS_WL, WS_WR, WS_WE};

    ld_tile(dsm, AHI_H, Ahi, 64, 0, rowBase, M - 1, tid);
    ld_tile(dsm, ALO_H, Alo, 64, 0, rowBase, M - 1, tid);
    ld_tile(dsm, BHI_H, ws + wsoff[0], 64, 0, 0, 127, tid);
    ld_tile(dsm, BLO_H, ws + wsoff[0] + 8192, 64, 0, 0, 127, tid);
    __syncthreads();

    const int gq = lane >> 2;
    const int c2 = (lane & 3) * 2;

#pragma unroll
    for (int t = 0; t < 3; t++) {
        float c[4][4][4];
#pragma unroll
        for (int i = 0; i < 4; i++)
#pragma unroll
            for (int j = 0; j < 4; j++)
#pragma unroll
                for (int q = 0; q < 4; q++) c[i][j][q] = 0.f;

        mma_chunk(sb, wm, wn, lane, c);

#pragma unroll
        for (int mi = 0; mi < 4; mi++) {
#pragma unroll
            for (int ni = 0; ni < 4; ni++) {
                int colg = wn * 32 + ni * 8 + c2;
                float2 bb = make_float2(0.f, 0.f);
                if (t == 0) bb = *(const float2*)&bl_[colg];
                else if (t == 1) bb = *(const float2*)&br_[colg];
#pragma unroll
                for (int half = 0; half < 2; half++) {
                    int gr = rowBase + wm * 64 + mi * 16 + gq + half * 8;
                    if (gr >= M) continue;
                    float v0 = c[mi][ni][half * 2 + 0] + bb.x;
                    float v1 = c[mi][ni][half * 2 + 1] + bb.y;
                    if (t == 0) {
                        *(float2*)&P[(size_t)gr * 384 + colg] = make_float2(v0, v1);
                    } else if (t == 1) {
                        *(float2*)&XR[(size_t)gr * 128 + colg] = make_float2(v0, v1);
                    } else {
                        float2 xl = *(const float2*)&P[(size_t)gr * 384 + colg];
                        float2 xr = *(const float2*)&XR[(size_t)gr * 128 + colg];
                        *(float2*)&P[(size_t)gr * 384 + 128 + colg] = make_float2(xl.x + v0, xl.y + v1);
                        *(float2*)&P[(size_t)gr * 384 + 256 + colg] = make_float2(xr.x - v0, xr.y - v1);
                    }
                }
            }
        }
        __syncthreads();
        if (t < 2) {
            ld_tile(dsm, BHI_H, ws + wsoff[t + 1], 64, 0, 0, 127, tid);
            ld_tile(dsm, BLO_H, ws + wsoff[t + 1] + 8192, 64, 0, 0, 127, tid);
            __syncthreads();
        }
    }
}

// ---------------- fused GAT attention: warp per dst node over CSR ----------------
__global__ void __launch_bounds__(256) k_attn(const float* __restrict__ pos,
                                              const float* __restrict__ We,
                                              const float* __restrict__ att, int E, int M) {
    int n = blockIdx.x * 8 + (threadIdx.x >> 5);
    if (n >= M) return;
    int l = threadIdx.x & 31;
    int h = l >> 3;
    const int* IA = csr_base();
    const int* list = IA;
    const int* off = IA + E;
    int off0 = off[n], off1 = off[n + 1];

    float2 pd = ((const float2*)pos)[n];
    float4 b4 = *(const float4*)(g_scratch + OFF_P + (size_t)n * 384 + 256 + 4 * l);
    float4 at = *(const float4*)(att + 4 * l);
    float4 c0 = *(const float4*)(We + 128 * 128 + 4 * l);
    float4 c1 = *(const float4*)(We + 129 * 128 + 4 * l);
    float* logit = g_scratch + OFF_LOGIT;

    float mh = -1e30f;
    for (int p = off0; p < off1; p++) {
        int s = list[p];
        float2 ps = ((const float2*)pos)[s];
        float rx = ps.x - pd.x, ry = ps.y - pd.y;
        float dsq = rx * rx + ry * ry + 1e-8f;
        float ox = -ry / dsq, oy = rx / dsq;
        float4 a4 = *(const float4*)(g_scratch + OFF_P + (size_t)s * 384 + 128 + 4 * l);
        float4 x;
        x.x = a4.x + b4.x + ox * c0.x + oy * c1.x;
        x.y = a4.y + b4.y + ox * c0.y + oy * c1.y;
        x.z = a4.z + b4.z + ox * c0.z + oy * c1.z;
        x.w = a4.w + b4.w + ox * c0.w + oy * c1.w;
        x.x = x.x > 0.f ? x.x : 0.2f * x.x;
        x.y = x.y > 0.f ? x.y : 0.2f * x.y;
        x.z = x.z > 0.f ? x.z : 0.2f * x.z;
        x.w = x.w > 0.f ? x.w : 0.2f * x.w;
        float lg = x.x * at.x + x.y * at.y + x.z * at.z + x.w * at.w;
        lg += __shfl_xor_sync(0xffffffffu, lg, 4);
        lg += __shfl_xor_sync(0xffffffffu, lg, 2);
        lg += __shfl_xor_sync(0xffffffffu, lg, 1);
        if ((l & 7) == 0) logit[(size_t)p * 4 + h] = lg;
        mh = fmaxf(mh, lg);
    }
    __syncwarp();

    float4 acc = make_float4(0.f, 0.f, 0.f, 0.f);
    float den = 0.f;
    for (int p = off0; p < off1; p++) {
        int s = list[p];
        float al = expf(logit[(size_t)p * 4 + h] - mh);
        den += al;
        float4 xl = *(const float4*)(g_scratch + OFF_P + (size_t)s * 384 + 4 * l);
        acc.x += xl.x * al;
        acc.y += xl.y * al;
        acc.z += xl.z * al;
        acc.w += xl.w * al;
    }
    float r = 1.f / (den + 1e-16f);
    acc.x *= r; acc.y *= r; acc.z *= r; acc.w *= r;

    uint32_t l0, l1;
    uint32_t h0 = pack_split(acc.x, acc.y, l0);
    uint32_t h1 = pack_split(acc.z, acc.w, l1);
    uint32_t* st = (uint32_t*)(g_scratch + OFF_HMOD);
    st[(size_t)n * 64 + 2 * l]     = h0;
    st[(size_t)n * 64 + 2 * l + 1] = h1;
    st[(size_t)NN * 64 + (size_t)n * 64 + 2 * l]     = l0;
    st[(size_t)NN * 64 + (size_t)n * 64 + 2 * l + 1] = l1;
}

// ---------------- LayerNorm -> packed bf16 hi/lo staging ----------------
__global__ void __launch_bounds__(256) k_ln(const float* __restrict__ lnw,
                                            const float* __restrict__ lnb, int M) {
    int n = blockIdx.x * 8 + (threadIdx.x >> 5);
    if (n >= M) return;
    int l = threadIdx.x & 31;
    float4 v = ((const float4*)(g_scratch + OFF_AGGR2 + (size_t)n * 128))[l];
    float s = v.x + v.y + v.z + v.w;
    float q = v.x * v.x + v.y * v.y + v.z * v.z + v.w * v.w;
#pragma unroll
    for (int o = 16; o; o >>= 1) {
        s += __shfl_xor_sync(0xffffffffu, s, o);
        q += __shfl_xor_sync(0xffffffffu, q, o);
    }
    float mean = s * (1.f / 128.f);
    float var  = q * (1.f / 128.f) - mean * mean;
    float rstd = rsqrtf(var + 1e-5f);
    float4 w = ((const float4*)lnw)[l];
    float4 b = ((const float4*)lnb)[l];
    float4 o4;
    o4.x = (v.x - mean) * rstd * w.x + b.x;
    o4.y = (v.y - mean) * rstd * w.y + b.y;
    o4.z = (v.z - mean) * rstd * w.z + b.z;
    o4.w = (v.w - mean) * rstd * w.w + b.w;
    uint32_t l0, l1;
    uint32_t h0 = pack_split(o4.x, o4.y, l0);
    uint32_t h1 = pack_split(o4.z, o4.w, l1);
    uint32_t* st = (uint32_t*)(g_scratch + OFF_HMOD);
    st[(size_t)n * 64 + 2 * l]     = h0;
    st[(size_t)n * 64 + 2 * l + 1] = h1;
    st[(size_t)NN * 64 + (size_t)n * 64 + 2 * l]     = l0;
    st[(size_t)NN * 64 + (size_t)n * 64 + 2 * l + 1] = l1;
}

// ---------------- launch ----------------
extern "C" void kernel_launch(void* const* d_in, const int* in_sizes, int n_in,
                              void* d_out, int out_size) {
    const float* h_target = (const float*)d_in[0];
    const float* h_source = (const float*)d_in[1];
    const int* ei      = (const int*)d_in[2];
    const float* pos   = (const float*)d_in[3];
    const float* t_emb = (const float*)d_in[4];
    const float* gn_w  = (const float*)d_in[5];
    const float* gn_b  = (const float*)d_in[6];
    const float* fcW   = (const float*)d_in[7];
    const float* fcb   = (const float*)d_in[8];
    const float* Wl    = (const float*)d_in[9];
    const float* bl    = (const float*)d_in[10];
    const float* Wr    = (const float*)d_in[11];
    const float* br    = (const float*)d_in[12];
    const float* We    = (const float*)d_in[13];
    const float* att   = (const float*)d_in[14];
    const float* gatb  = (const float*)d_in[15];
    const float* Wp    = (const float*)d_in[16];
    const float* bp    = (const float*)d_in[17];
    const float* lnw   = (const float*)d_in[18];
    const float* lnb   = (const float*)d_in[19];
    const float* W1    = (const float*)d_in[20];
    const float* b1    = (const float*)d_in[21];
    const float* W2    = (const float*)d_in[22];
    const float* b2    = (const float*)d_in[23];

    int M = in_sizes[0] / 128; if (M > NN) M = NN;
    int E = in_sizes[2] / 2;   if (E > EE) E = EE;

    float* sc = nullptr;
    cudaGetSymbolAddress((void**)&sc, g_scratch);
    float* P     = sc + OFF_P;
    float* AGGR2 = sc + OFF_AGGR2;
    float* BIAS2 = sc + OFF_BIAS2;
    uint32_t* HMB  = (uint32_t*)(sc + OFF_HMOD);
    uint32_t* Z1HI = (uint32_t*)(sc + OFF_P) + (size_t)NN * 128;
    uint32_t* Z1LO = Z1HI + (size_t)NN * 128;
    uint32_t* WS   = (uint32_t*)(sc + OFF_WSTG);

    cudaFuncSetAttribute(k_mma,  cudaFuncAttributeMaxDynamicSharedMemorySize, SMEM_BYTES);
    cudaFuncSetAttribute(k_mma3, cudaFuncAttributeMaxDynamicSharedMemorySize, SMEM_BYTES);

    dim3 blk(256);
    dim3 g1((M + 127) / 128, 1);
    dim3 g2((M + 127) / 128, 2);

    k_detect<<<1, 1>>>(ei);
    k_style<<<1, 384>>>(t_emb, fcW, fcb, gatb, Wp, bp);
    // CSR build
    k_zdeg<<<(M + 255) / 256, 256>>>(E, M);
    k_prep<<<(E + 255) / 256, 256>>>(ei, E, M);
    k_scan<<<1, 1024>>>(E, M);
    k_fill<<<(E + 255) / 256, 256>>>(ei, E, M);
    // stage weights
    k_wconv<<<32, 256>>>(Wl, 128, 128, WS_WL);
    k_wconv<<<32, 256>>>(Wr, 128, 128, WS_WR);
    k_wconv<<<32, 256>>>(We, 128, 128, WS_WE);
    k_wconv<<<32, 256>>>(Wp, 128, 128, WS_WP);
    k_wconv<<<64, 256>>>(W1, 128, 256, WS_W1);
    k_wconv<<<64, 256>>>(W2, 256, 128, WS_W2);

    k_adagn<<<(M + 1) / 2, 256>>>(h_source, gn_w, gn_b, M);

    // fused node transforms: x_l->P, x_r->AGGR2(temp), combine->P+128/P+256
    k_mma3<<<g1, blk, SMEM_BYTES>>>(HMB, HMB + (size_t)NN * 64, bl, br, P, AGGR2, M);

    // fused GAT: logits+softmax+aggregate -> HMOD (bf16 hi/lo)
    k_attn<<<(M + 7) / 8, 256>>>(pos, We, att, E, M);

    // post_gat: aggr(bf16)@Wp + bias2 -> AGGR2 fp32
    k_mma<<<g1, blk, SMEM_BYTES>>>(HMB, HMB + (size_t)NN * 64, 64,
                                   WS + WS_WP, WS + WS_WP + 8192, 64,
                                   BIAS2, 0, AGGR2, 128, nullptr, nullptr, nullptr, 0, M, 128);
    k_ln<<<(M + 7) / 8, 256>>>(lnw, lnb, M);
    // W1 + GELU -> z1 bf16
    k_mma<<<g2, blk, SMEM_BYTES>>>(HMB, HMB + (size_t)NN * 64, 64,
                                   WS + WS_W1, WS + WS_W1 + 16384, 64,
                                   b1, 1, nullptr, 0, nullptr, Z1HI, Z1LO, 128, M, 128);
    // W2 + residual -> d_out
    k_mma<<<g1, blk, SMEM_BYTES>>>(Z1HI, Z1LO, 128,
                                   WS + WS_W2, WS + WS_W2 + 16384, 128,
                                   b2, 2, (float*)d_out, 128, h_target, nullptr, nullptr, 0, M, 256);
}

// round 15
// speedup vs baseline: 2.1741x; 1.0976x over previous
#include <cuda_runtime.h>
#include <cuda_bf16.h>
#include <cstdint>
#include <cstddef>

#define NN 50000
#define EE 800000

// ---------------- scratch layout (floats) ----------------
constexpr size_t OFF_P     = 0;                              // N*384 edge rows; later z1 bf16 hi/lo
constexpr size_t OFF_HMOD  = OFF_P     + (size_t)NN * 384;   // bf16 hi/lo staging
constexpr size_t OFF_LOGIT = OFF_HMOD  + (size_t)NN * 128;   // (unused now)
constexpr size_t OFF_AMAX  = OFF_LOGIT + (size_t)EE * 4;
constexpr size_t OFF_DENOM = OFF_AMAX  + (size_t)NN * 4;
constexpr size_t OFF_AGGR  = OFF_DENOM + (size_t)NN * 4;     // CSR int arrays
constexpr size_t OFF_AGGR2 = OFF_AGGR  + (size_t)NN * 128;   // x_r temp, then Wp out fp32
constexpr size_t OFF_STYLE = OFF_AGGR2 + (size_t)NN * 128;   // 256
constexpr size_t OFF_BIAS2 = OFF_STYLE + 256;                // 128
constexpr size_t OFF_ZERO  = OFF_BIAS2 + 128;                // 128
constexpr size_t OFF_WSTG  = OFF_ZERO + 128;                 // 131072 uint32 staged weights
constexpr size_t SCRATCH_TOTAL = OFF_WSTG + 131072;

constexpr int WS_WL = 0;
constexpr int WS_WR = 16384;
constexpr int WS_WE = 32768;
constexpr int WS_WP = 49152;
constexpr int WS_W1 = 65536;
constexpr int WS_W2 = 98304;

__device__ __align__(16) float g_scratch[SCRATCH_TOTAL];
__device__ int g_is64;

__device__ __forceinline__ int* csr_base() { return (int*)(g_scratch + OFF_AGGR); }

// ---------------- helpers ----------------
__device__ __forceinline__ float geluf(float x) {
    return 0.5f * x * (1.f + erff(x * 0.70710678118654752440f));
}
__device__ __forceinline__ int eidx(const int* __restrict__ ei32, size_t pos, int is64, int M) {
    int v = ei32[is64 ? (pos << 1) : pos];
    if ((unsigned)v >= (unsigned)M) v = 0;
    return v;
}
__device__ __forceinline__ uint32_t s2u(const void* p) {
    uint32_t a;
    asm("{ .reg .u64 t; cvta.to.shared.u64 t, %1; cvt.u32.u64 %0, t; }" : "=r"(a) : "l"(p));
    return a;
}
__device__ __forceinline__ void ldsm_x4(uint32_t& r0, uint32_t& r1, uint32_t& r2, uint32_t& r3, uint32_t addr) {
    asm volatile("ldmatrix.sync.aligned.m8n8.x4.shared.b16 {%0,%1,%2,%3}, [%4];"
                 : "=r"(r0), "=r"(r1), "=r"(r2), "=r"(r3) : "r"(addr));
}
__device__ __forceinline__ void ldsm_x2(uint32_t& r0, uint32_t& r1, uint32_t addr) {
    asm volatile("ldmatrix.sync.aligned.m8n8.x2.shared.b16 {%0,%1}, [%2];"
                 : "=r"(r0), "=r"(r1) : "r"(addr));
}
__device__ __forceinline__ void mma_bf16(float* c, uint32_t a0, uint32_t a1, uint32_t a2, uint32_t a3,
                                         uint32_t b0, uint32_t b1) {
    asm volatile("mma.sync.aligned.m16n8k16.row.col.f32.bf16.bf16.f32 "
                 "{%0,%1,%2,%3}, {%4,%5,%6,%7}, {%8,%9}, {%0,%1,%2,%3};"
                 : "+f"(c[0]), "+f"(c[1]), "+f"(c[2]), "+f"(c[3])
                 : "r"(a0), "r"(a1), "r"(a2), "r"(a3), "r"(b0), "r"(b1));
}
__device__ __forceinline__ uint32_t pack_split(float a, float b, uint32_t& lo) {
    __nv_bfloat16 ha = __float2bfloat16(a), hb = __float2bfloat16(b);
    float ra = a - __bfloat162float(ha), rb = b - __bfloat162float(hb);
    __nv_bfloat16 la = __float2bfloat16(ra), lb = __float2bfloat16(rb);
    unsigned short uha = *(unsigned short*)&ha, uhb = *(unsigned short*)&hb;
    unsigned short ula = *(unsigned short*)&la, ulb = *(unsigned short*)&lb;
    lo = (uint32_t)ula | ((uint32_t)ulb << 16);
    return (uint32_t)uha | ((uint32_t)uhb << 16);
}

// ---------------- detect edge_index dtype ----------------
__global__ void k_detect(const int* __restrict__ ei32) {
    int z = 0;
#pragma unroll
    for (int i = 0; i < 16; i++) z |= ei32[2 * i + 1];
    g_is64 = (z == 0) ? 1 : 0;
}

// ---------------- CSR build ----------------
__global__ void k_zdeg(int E, int M) {
    int i = blockIdx.x * 256 + threadIdx.x;
    if (i < M) csr_base()[E + M + 1 + i] = 0;
}
__global__ void k_prep(const int* __restrict__ ei, int E, int M) {
    int e = blockIdx.x * 256 + threadIdx.x;
    if (e >= E) return;
    int d = eidx(ei, (size_t)E + e, g_is64, M);
    atomicAdd(&csr_base()[E + M + 1 + d], 1);
}
__global__ void __launch_bounds__(1024) k_scan(int E, int M) {
    __shared__ int ssum[1024];
    int* IA = csr_base();
    int* off = IA + E;
    int* cur = IA + E + M + 1;
    int t = threadIdx.x;
    int C = (M + 1023) >> 10;
    int lo = t * C, hi = lo + C; if (hi > M) hi = M; if (lo > M) lo = M;
    int s = 0;
    for (int i = lo; i < hi; i++) s += cur[i];
    ssum[t] = s;
    __syncthreads();
    for (int o = 1; o < 1024; o <<= 1) {
        int v = (t >= o) ? ssum[t - o] : 0;
        __syncthreads();
        ssum[t] += v;
        __syncthreads();
    }
    int pre = (t == 0) ? 0 : ssum[t - 1];
    for (int i = lo; i < hi; i++) {
        int d = cur[i];
        off[i] = pre;
        cur[i] = pre;
        pre += d;
    }
    if (t == 1023) off[M] = ssum[1023];
}
__global__ void k_fill(const int* __restrict__ ei, int E, int M) {
    int e = blockIdx.x * 256 + threadIdx.x;
    if (e >= E) return;
    int is64 = g_is64;
    int s = eidx(ei, (size_t)e, is64, M);
    int d = eidx(ei, (size_t)E + e, is64, M);
    int* IA = csr_base();
    int p = atomicAdd(&IA[E + M + 1 + d], 1);
    IA[p] = s;
}

// ---------------- weight convert ----------------
__global__ void k_wconv(const float* __restrict__ W, int kdim, int ndim, int dstOff) {
    int t = blockIdx.x * 256 + threadIdx.x;
    int kh = kdim >> 1;
    int tot = ndim * kh;
    if (t >= tot) return;
    int n = t / kh, kp = t % kh;
    float a = W[(size_t)(2 * kp) * ndim + n];
    float b = W[(size_t)(2 * kp + 1) * ndim + n];
    uint32_t l, h = pack_split(a, b, l);
    uint32_t* ws = (uint32_t*)(g_scratch + OFF_WSTG) + dstOff;
    ws[(size_t)n * kh + kp] = h;
    ws[(size_t)tot + (size_t)n * kh + kp] = l;
}

// ---------------- tiny precompute ----------------
__global__ void k_style(const float* __restrict__ t_emb, const float* __restrict__ fcW,
                        const float* __restrict__ fcb, const float* __restrict__ gatb,
                        const float* __restrict__ Wp, const float* __restrict__ bp) {
    int j = threadIdx.x;
    if (j < 256) {
        float s = fcb[j];
        for (int i = 0; i < 128; i++) s += t_emb[i] * fcW[i * 256 + j];
        g_scratch[OFF_STYLE + j] = s;
    } else if (j < 384) {
        int c = j - 256;
        float s = bp[c];
        for (int i = 0; i < 128; i++) s += gatb[i] * Wp[i * 128 + c];
        g_scratch[OFF_BIAS2 + c] = s;
    }
}

// ---------------- AdaGN (warp per node, float4) -> packed bf16 hi/lo ----------------
__global__ void __launch_bounds__(256) k_adagn(const float* __restrict__ hs,
                                               const float* __restrict__ gnw,
                                               const float* __restrict__ gnb, int M) {
    int n = blockIdx.x * 8 + (threadIdx.x >> 5);
    if (n >= M) return;
    int l = threadIdx.x & 31;
    float4 v = ((const float4*)(hs + (size_t)n * 128))[l];
    // group of 16 channels = 4 consecutive lanes (l&~3)
    float s = v.x + v.y + v.z + v.w;
    float q = v.x * v.x + v.y * v.y + v.z * v.z + v.w * v.w;
    s += __shfl_xor_sync(0xffffffffu, s, 1);
    q += __shfl_xor_sync(0xffffffffu, q, 1);
    s += __shfl_xor_sync(0xffffffffu, s, 2);
    q += __shfl_xor_sync(0xffffffffu, q, 2);
    float mean = s * (1.f / 16.f);
    float var  = q * (1.f / 16.f) - mean * mean;
    float rstd = rsqrtf(var + 1e-5f);
    int c = 4 * l;
    float4 w4 = *(const float4*)&gnw[c];
    float4 b4 = *(const float4*)&gnb[c];
    float4 g4 = *(const float4*)&g_scratch[OFF_STYLE + c];
    float4 e4 = *(const float4*)&g_scratch[OFF_STYLE + 128 + c];
    float h0 = ((v.x - mean) * rstd * w4.x + b4.x) * (1.f + g4.x) + e4.x;
    float h1 = ((v.y - mean) * rstd * w4.y + b4.y) * (1.f + g4.y) + e4.y;
    float h2 = ((v.z - mean) * rstd * w4.z + b4.z) * (1.f + g4.z) + e4.z;
    float h3 = ((v.w - mean) * rstd * w4.w + b4.w) * (1.f + g4.w) + e4.w;
    uint32_t l0, l1;
    uint32_t p0 = pack_split(h0, h1, l0);
    uint32_t p1 = pack_split(h2, h3, l1);
    uint32_t* st = (uint32_t*)(g_scratch + OFF_HMOD);
    st[(size_t)n * 64 + 2 * l]     = p0;
    st[(size_t)n * 64 + 2 * l + 1] = p1;
    st[(size_t)NN * 64 + (size_t)n * 64 + 2 * l]     = l0;
    st[(size_t)NN * 64 + (size_t)n * 64 + 2 * l + 1] = l1;
}

// ======================================================================
// HMMA bf16 3-term split GEMM core
// ======================================================================
constexpr int SLDA  = 136;
constexpr int TILEH = 128 * SLDA;
constexpr int AHI_H = 0;
constexpr int ALO_H = TILEH;
constexpr int BHI_H = 2 * TILEH;
constexpr int BLO_H = 3 * TILEH;
constexpr int SMEM_BYTES = 4 * TILEH * 2;

__device__ __forceinline__ void ld_tile(char* dsm, int half_base, const uint32_t* __restrict__ src,
                                        int ld32, int k32off, int rowBase, int rowMax, int tid) {
#pragma unroll
    for (int it = 0; it < 8; it++) {
        int idx = it * 256 + tid;
        int row = idx >> 4, c16 = idx & 15;
        int gr = rowBase + row;
        if (gr > rowMax) gr = rowMax;
        uint4 v = *(const uint4*)(src + (size_t)gr * ld32 + k32off + c16 * 4);
        *(uint4*)(dsm + 2 * (half_base + row * SLDA) + c16 * 16) = v;
    }
}

__device__ __forceinline__ void mma_chunk(uint32_t sb, int wm, int wn, int lane, float c[4][4][4]) {
    const int lrA = lane & 15, lcA = (lane >> 4) << 3;
    const int lrB = lane & 7,  lcB = ((lane >> 3) & 1) << 3;
#pragma unroll
    for (int ks = 0; ks < 8; ks++) {
        uint32_t ah[4][4], al[4][4];
#pragma unroll
        for (int mi = 0; mi < 4; mi++) {
            uint32_t addr = sb + 2u * (uint32_t)((wm * 64 + mi * 16 + lrA) * SLDA + ks * 16 + lcA);
            ldsm_x4(ah[mi][0], ah[mi][1], ah[mi][2], ah[mi][3], addr);
            ldsm_x4(al[mi][0], al[mi][1], al[mi][2], al[mi][3], addr + 2u * (uint32_t)ALO_H);
        }
#pragma unroll
        for (int ni = 0; ni < 4; ni++) {
            uint32_t baddr = sb + 2u * (uint32_t)(BHI_H + (wn * 32 + ni * 8 + lrB) * SLDA + ks * 16 + lcB);
            uint32_t bh0, bh1, bl0, bl1;
            ldsm_x2(bh0, bh1, baddr);
            ldsm_x2(bl0, bl1, baddr + 2u * (uint32_t)(BLO_H - BHI_H));
#pragma unroll
            for (int mi = 0; mi < 4; mi++) {
                mma_bf16(c[mi][ni], ah[mi][0], ah[mi][1], ah[mi][2], ah[mi][3], bh0, bh1);
                mma_bf16(c[mi][ni], al[mi][0], al[mi][1], al[mi][2], al[mi][3], bh0, bh1);
                mma_bf16(c[mi][ni], ah[mi][0], ah[mi][1], ah[mi][2], ah[mi][3], bl0, bl1);
            }
        }
    }
}

// generic GEMM: modes 0 plain fp32, 1 GELU->packed bf16, 2 fp32 + extra residual
__global__ void __launch_bounds__(256, 1) k_mma(
    const uint32_t* __restrict__ Ahi, const uint32_t* __restrict__ Alo, int lda32,
    const uint32_t* __restrict__ Bhi, const uint32_t* __restrict__ Blo, int ldb32,
    const float* __restrict__ bias, int mode,
    float* __restrict__ Cf, int ldc, const float* __restrict__ extra,
    uint32_t* __restrict__ Cohi, uint32_t* __restrict__ Colo, int ldco,
    int M, int K)
{
    extern __shared__ __align__(16) char dsm[];
    const int tid = threadIdx.x;
    const int w = tid >> 5, lane = tid & 31;
    const uint32_t sb = s2u(dsm);
    const int rowBase = blockIdx.x * 128;
    const int nBase = blockIdx.y * 128;
    const int wm = w & 1, wn = w >> 1;

    const uint32_t* bh = Bhi + (size_t)nBase * ldb32;
    const uint32_t* bl = Blo + (size_t)nBase * ldb32;

    float c[4][4][4];
#pragma unroll
    for (int i = 0; i < 4; i++)
#pragma unroll
        for (int j = 0; j < 4; j++)
#pragma unroll
            for (int q = 0; q < 4; q++) c[i][j][q] = 0.f;

    for (int kt = 0; kt < K; kt += 128) {
        int k32 = kt >> 1;
        ld_tile(dsm, AHI_H, Ahi, lda32, k32, rowBase, M - 1, tid);
        ld_tile(dsm, ALO_H, Alo, lda32, k32, rowBase, M - 1, tid);
        ld_tile(dsm, BHI_H, bh, ldb32, k32, 0, 127, tid);
        ld_tile(dsm, BLO_H, bl, ldb32, k32, 0, 127, tid);
        __syncthreads();
        mma_chunk(sb, wm, wn, lane, c);
        __syncthreads();
    }

    const int gq = lane >> 2;
    const int c2 = (lane & 3) * 2;
#pragma unroll
    for (int mi = 0; mi < 4; mi++) {
#pragma unroll
        for (int ni = 0; ni < 4; ni++) {
            int colg = nBase + wn * 32 + ni * 8 + c2;
            float2 bb = *(const float2*)&bias[colg];
#pragma unroll
            for (int half = 0; half < 2; half++) {
                int gr = rowBase + wm * 64 + mi * 16 + gq + half * 8;
                if (gr >= M) continue;
                float v0 = c[mi][ni][half * 2 + 0] + bb.x;
                float v1 = c[mi][ni][half * 2 + 1] + bb.y;
                if (mode == 0) {
                    *(float2*)&Cf[(size_t)gr * ldc + colg] = make_float2(v0, v1);
                } else if (mode == 1) {
                    uint32_t l, h = pack_split(geluf(v0), geluf(v1), l);
                    Cohi[(size_t)gr * ldco + (colg >> 1)] = h;
                    Colo[(size_t)gr * ldco + (colg >> 1)] = l;
                } else {
                    float2 r4 = *(const float2*)&extra[(size_t)gr * 128 + colg];
                    *(float2*)&Cf[(size_t)gr * ldc + colg] = make_float2(v0 + r4.x, v1 + r4.y);
                }
            }
        }
    }
}

// fused node-transform GEMM: A (HM bf16) loaded once, loop over Wl/Wr/We
__global__ void __launch_bounds__(256, 1) k_mma3(
    const uint32_t* __restrict__ Ahi, const uint32_t* __restrict__ Alo,
    const float* __restrict__ bl_, const float* __restrict__ br_,
    float* __restrict__ P, float* __restrict__ XR, int M)
{
    extern __shared__ __align__(16) char dsm[];
    const int tid = threadIdx.x;
    const int w = tid >> 5, lane = tid & 31;
    const uint32_t sb = s2u(dsm);
    const int rowBase = blockIdx.x * 128;
    const int wm = w & 1, wn = w >> 1;
    const uint32_t* ws = (const uint32_t*)(g_scratch + OFF_WSTG);
    const int wsoff[3] = {WS_WL, WS_WR, WS_WE};

    ld_tile(dsm, AHI_H, Ahi, 64, 0, rowBase, M - 1, tid);
    ld_tile(dsm, ALO_H, Alo, 64, 0, rowBase, M - 1, tid);
    ld_tile(dsm, BHI_H, ws + wsoff[0], 64, 0, 0, 127, tid);
    ld_tile(dsm, BLO_H, ws + wsoff[0] + 8192, 64, 0, 0, 127, tid);
    __syncthreads();

    const int gq = lane >> 2;
    const int c2 = (lane & 3) * 2;

#pragma unroll
    for (int t = 0; t < 3; t++) {
        float c[4][4][4];
#pragma unroll
        for (int i = 0; i < 4; i++)
#pragma unroll
            for (int j = 0; j < 4; j++)
#pragma unroll
                for (int q = 0; q < 4; q++) c[i][j][q] = 0.f;

        mma_chunk(sb, wm, wn, lane, c);

#pragma unroll
        for (int mi = 0; mi < 4; mi++) {
#pragma unroll
            for (int ni = 0; ni < 4; ni++) {
                int colg = wn * 32 + ni * 8 + c2;
                float2 bb = make_float2(0.f, 0.f);
                if (t == 0) bb = *(const float2*)&bl_[colg];
                else if (t == 1) bb = *(const float2*)&br_[colg];
#pragma unroll
                for (int half = 0; half < 2; half++) {
                    int gr = rowBase + wm * 64 + mi * 16 + gq + half * 8;
                    if (gr >= M) continue;
                    float v0 = c[mi][ni][half * 2 + 0] + bb.x;
                    float v1 = c[mi][ni][half * 2 + 1] + bb.y;
                    if (t == 0) {
                        *(float2*)&P[(size_t)gr * 384 + colg] = make_float2(v0, v1);
                    } else if (t == 1) {
                        *(float2*)&XR[(size_t)gr * 128 + colg] = make_float2(v0, v1);
                    } else {
                        float2 xl = *(const float2*)&P[(size_t)gr * 384 + colg];
                        float2 xr = *(const float2*)&XR[(size_t)gr * 128 + colg];
                        *(float2*)&P[(size_t)gr * 384 + 128 + colg] = make_float2(xl.x + v0, xl.y + v1);
                        *(float2*)&P[(size_t)gr * 384 + 256 + colg] = make_float2(xr.x - v0, xr.y - v1);
                    }
                }
            }
        }
        __syncthreads();
        if (t < 2) {
            ld_tile(dsm, BHI_H, ws + wsoff[t + 1], 64, 0, 0, 127, tid);
            ld_tile(dsm, BLO_H, ws + wsoff[t + 1] + 8192, 64, 0, 0, 127, tid);
            __syncthreads();
        }
    }
}

// ---------------- fused GAT attention: single-pass online softmax ----------------
__global__ void __launch_bounds__(256) k_attn(const float* __restrict__ pos,
                                              const float* __restrict__ We,
                                              const float* __restrict__ att, int E, int M) {
    int n = blockIdx.x * 8 + (threadIdx.x >> 5);
    if (n >= M) return;
    int l = threadIdx.x & 31;
    const int* list = csr_base();
    const int* off = list + E;
    int off0 = off[n], off1 = off[n + 1];

    float2 pd = ((const float2*)pos)[n];
    float4 b4 = *(const float4*)(g_scratch + OFF_P + (size_t)n * 384 + 256 + 4 * l);
    float4 at = *(const float4*)(att + 4 * l);
    float4 c0 = *(const float4*)(We + 128 * 128 + 4 * l);
    float4 c1 = *(const float4*)(We + 129 * 128 + 4 * l);

    float mh = -1e30f, den = 0.f;
    float4 acc = make_float4(0.f, 0.f, 0.f, 0.f);
    for (int p = off0; p < off1; p++) {
        int s = list[p];
        float2 ps = ((const float2*)pos)[s];
        const float* rowp = g_scratch + OFF_P + (size_t)s * 384;
        float4 a4 = *(const float4*)(rowp + 128 + 4 * l);
        float4 xl = *(const float4*)(rowp + 4 * l);
        float rx = ps.x - pd.x, ry = ps.y - pd.y;
        float dsq = rx * rx + ry * ry + 1e-8f;
        float ox = -ry / dsq, oy = rx / dsq;
        float4 x;
        x.x = a4.x + b4.x + ox * c0.x + oy * c1.x;
        x.y = a4.y + b4.y + ox * c0.y + oy * c1.y;
        x.z = a4.z + b4.z + ox * c0.z + oy * c1.z;
        x.w = a4.w + b4.w + ox * c0.w + oy * c1.w;
        x.x = x.x > 0.f ? x.x : 0.2f * x.x;
        x.y = x.y > 0.f ? x.y : 0.2f * x.y;
        x.z = x.z > 0.f ? x.z : 0.2f * x.z;
        x.w = x.w > 0.f ? x.w : 0.2f * x.w;
        float lg = x.x * at.x + x.y * at.y + x.z * at.z + x.w * at.w;
        lg += __shfl_xor_sync(0xffffffffu, lg, 4);
        lg += __shfl_xor_sync(0xffffffffu, lg, 2);
        lg += __shfl_xor_sync(0xffffffffu, lg, 1);
        float mnew = fmaxf(mh, lg);
        float scale = expf(mh - mnew);
        float al = expf(lg - mnew);
        den = den * scale + al;
        acc.x = acc.x * scale + xl.x * al;
        acc.y = acc.y * scale + xl.y * al;
        acc.z = acc.z * scale + xl.z * al;
        acc.w = acc.w * scale + xl.w * al;
        mh = mnew;
    }
    float r = 1.f / (den + 1e-16f);
    acc.x *= r; acc.y *= r; acc.z *= r; acc.w *= r;

    uint32_t l0, l1;
    uint32_t h0 = pack_split(acc.x, acc.y, l0);
    uint32_t h1 = pack_split(acc.z, acc.w, l1);
    uint32_t* st = (uint32_t*)(g_scratch + OFF_HMOD);
    st[(size_t)n * 64 + 2 * l]     = h0;
    st[(size_t)n * 64 + 2 * l + 1] = h1;
    st[(size_t)NN * 64 + (size_t)n * 64 + 2 * l]     = l0;
    st[(size_t)NN * 64 + (size_t)n * 64 + 2 * l + 1] = l1;
}

// ---------------- LayerNorm -> packed bf16 hi/lo staging ----------------
__global__ void __launch_bounds__(256) k_ln(const float* __restrict__ lnw,
                                            const float* __restrict__ lnb, int M) {
    int n = blockIdx.x * 8 + (threadIdx.x >> 5);
    if (n >= M) return;
    int l = threadIdx.x & 31;
    float4 v = ((const float4*)(g_scratch + OFF_AGGR2 + (size_t)n * 128))[l];
    float s = v.x + v.y + v.z + v.w;
    float q = v.x * v.x + v.y * v.y + v.z * v.z + v.w * v.w;
#pragma unroll
    for (int o = 16; o; o >>= 1) {
        s += __shfl_xor_sync(0xffffffffu, s, o);
        q += __shfl_xor_sync(0xffffffffu, q, o);
    }
    float mean = s * (1.f / 128.f);
    float var  = q * (1.f / 128.f) - mean * mean;
    float rstd = rsqrtf(var + 1e-5f);
    float4 w = ((const float4*)lnw)[l];
    float4 b = ((const float4*)lnb)[l];
    float4 o4;
    o4.x = (v.x - mean) * rstd * w.x + b.x;
    o4.y = (v.y - mean) * rstd * w.y + b.y;
    o4.z = (v.z - mean) * rstd * w.z + b.z;
    o4.w = (v.w - mean) * rstd * w.w + b.w;
    uint32_t l0, l1;
    uint32_t h0 = pack_split(o4.x, o4.y, l0);
    uint32_t h1 = pack_split(o4.z, o4.w, l1);
    uint32_t* st = (uint32_t*)(g_scratch + OFF_HMOD);
    st[(size_t)n * 64 + 2 * l]     = h0;
    st[(size_t)n * 64 + 2 * l + 1] = h1;
    st[(size_t)NN * 64 + (size_t)n * 64 + 2 * l]     = l0;
    st[(size_t)NN * 64 + (size_t)n * 64 + 2 * l + 1] = l1;
}

// ---------------- launch ----------------
extern "C" void kernel_launch(void* const* d_in, const int* in_sizes, int n_in,
                              void* d_out, int out_size) {
    const float* h_target = (const float*)d_in[0];
    const float* h_source = (const float*)d_in[1];
    const int* ei      = (const int*)d_in[2];
    const float* pos   = (const float*)d_in[3];
    const float* t_emb = (const float*)d_in[4];
    const float* gn_w  = (const float*)d_in[5];
    const float* gn_b  = (const float*)d_in[6];
    const float* fcW   = (const float*)d_in[7];
    const float* fcb   = (const float*)d_in[8];
    const float* Wl    = (const float*)d_in[9];
    const float* bl    = (const float*)d_in[10];
    const float* Wr    = (const float*)d_in[11];
    const float* br    = (const float*)d_in[12];
    const float* We    = (const float*)d_in[13];
    const float* att   = (const float*)d_in[14];
    const float* gatb  = (const float*)d_in[15];
    const float* Wp    = (const float*)d_in[16];
    const float* bp    = (const float*)d_in[17];
    const float* lnw   = (const float*)d_in[18];
    const float* lnb   = (const float*)d_in[19];
    const float* W1    = (const float*)d_in[20];
    const float* b1    = (const float*)d_in[21];
    const float* W2    = (const float*)d_in[22];
    const float* b2    = (const float*)d_in[23];

    int M = in_sizes[0] / 128; if (M > NN) M = NN;
    int E = in_sizes[2] / 2;   if (E > EE) E = EE;

    float* sc = nullptr;
    cudaGetSymbolAddress((void**)&sc, g_scratch);
    float* P     = sc + OFF_P;
    float* AGGR2 = sc + OFF_AGGR2;
    float* BIAS2 = sc + OFF_BIAS2;
    uint32_t* HMB  = (uint32_t*)(sc + OFF_HMOD);
    uint32_t* Z1HI = (uint32_t*)(sc + OFF_P) + (size_t)NN * 128;
    uint32_t* Z1LO = Z1HI + (size_t)NN * 128;
    uint32_t* WS   = (uint32_t*)(sc + OFF_WSTG);

    cudaFuncSetAttribute(k_mma,  cudaFuncAttributeMaxDynamicSharedMemorySize, SMEM_BYTES);
    cudaFuncSetAttribute(k_mma3, cudaFuncAttributeMaxDynamicSharedMemorySize, SMEM_BYTES);

    dim3 blk(256);
    dim3 g1((M + 127) / 128, 1);
    dim3 g2((M + 127) / 128, 2);

    k_detect<<<1, 1>>>(ei);
    k_style<<<1, 384>>>(t_emb, fcW, fcb, gatb, Wp, bp);
    // CSR build
    k_zdeg<<<(M + 255) / 256, 256>>>(E, M);
    k_prep<<<(E + 255) / 256, 256>>>(ei, E, M);
    k_scan<<<1, 1024>>>(E, M);
    k_fill<<<(E + 255) / 256, 256>>>(ei, E, M);
    // stage weights
    k_wconv<<<32, 256>>>(Wl, 128, 128, WS_WL);
    k_wconv<<<32, 256>>>(Wr, 128, 128, WS_WR);
    k_wconv<<<32, 256>>>(We, 128, 128, WS_WE);
    k_wconv<<<32, 256>>>(Wp, 128, 128, WS_WP);
    k_wconv<<<64, 256>>>(W1, 128, 256, WS_W1);
    k_wconv<<<64, 256>>>(W2, 256, 128, WS_W2);

    k_adagn<<<(M + 7) / 8, 256>>>(h_source, gn_w, gn_b, M);

    // fused node transforms: x_l->P, x_r->AGGR2(temp), combine->P+128/P+256
    k_mma3<<<g1, blk, SMEM_BYTES>>>(HMB, HMB + (size_t)NN * 64, bl, br, P, AGGR2, M);

    // fused GAT: single-pass online softmax -> HMOD (bf16 hi/lo)
    k_attn<<<(M + 7) / 8, 256>>>(pos, We, att, E, M);

    // post_gat: aggr(bf16)@Wp + bias2 -> AGGR2 fp32
    k_mma<<<g1, blk, SMEM_BYTES>>>(HMB, HMB + (size_t)NN * 64, 64,
                                   WS + WS_WP, WS + WS_WP + 8192, 64,
                                   BIAS2, 0, AGGR2, 128, nullptr, nullptr, nullptr, 0, M, 128);
    k_ln<<<(M + 7) / 8, 256>>>(lnw, lnb, M);
    // W1 + GELU -> z1 bf16
    k_mma<<<g2, blk, SMEM_BYTES>>>(HMB, HMB + (size_t)NN * 64, 64,
                                   WS + WS_W1, WS + WS_W1 + 16384, 64,
                                   b1, 1, nullptr, 0, nullptr, Z1HI, Z1LO, 128, M, 128);
    // W2 + residual -> d_out
    k_mma<<<g1, blk, SMEM_BYTES>>>(Z1HI, Z1LO, 128,
                                   WS + WS_W2, WS + WS_W2 + 16384, 128,
                                   b2, 2, (float*)d_out, 128, h_target, nullptr, nullptr, 0, M, 256);
}

// round 16
// speedup vs baseline: 2.3747x; 1.0923x over previous
#include <cuda_runtime.h>
#include <cuda_bf16.h>
#include <cstdint>
#include <cstddef>

#define NN 50000
#define EE 800000

// ---------------- scratch layout (floats) ----------------
constexpr size_t OFF_P     = 0;                              // N*384 edge rows; later z1 bf16 hi/lo
constexpr size_t OFF_HMOD  = OFF_P     + (size_t)NN * 384;   // bf16 hi/lo staging
constexpr size_t OFF_LOGIT = OFF_HMOD  + (size_t)NN * 128;   // (unused)
constexpr size_t OFF_AMAX  = OFF_LOGIT + (size_t)EE * 4;
constexpr size_t OFF_DENOM = OFF_AMAX  + (size_t)NN * 4;
constexpr size_t OFF_AGGR  = OFF_DENOM + (size_t)NN * 4;     // CSR int arrays
constexpr size_t OFF_AGGR2 = OFF_AGGR  + (size_t)NN * 128;   // x_r temp, then Wp out fp32
constexpr size_t OFF_STYLE = OFF_AGGR2 + (size_t)NN * 128;   // 256
constexpr size_t OFF_BIAS2 = OFF_STYLE + 256;                // 128
constexpr size_t OFF_ZERO  = OFF_BIAS2 + 128;                // 128
constexpr size_t OFF_WSTG  = OFF_ZERO + 128;                 // 131072 uint32 staged weights
constexpr size_t SCRATCH_TOTAL = OFF_WSTG + 131072;

constexpr int WS_WL = 0;
constexpr int WS_WR = 16384;
constexpr int WS_WE = 32768;
constexpr int WS_WP = 49152;
constexpr int WS_W1 = 65536;
constexpr int WS_W2 = 98304;

__device__ __align__(16) float g_scratch[SCRATCH_TOTAL];
__device__ int g_is64;

__device__ __forceinline__ int* csr_base() { return (int*)(g_scratch + OFF_AGGR); }

// ---------------- helpers ----------------
__device__ __forceinline__ float geluf(float x) {
    return 0.5f * x * (1.f + erff(x * 0.70710678118654752440f));
}
__device__ __forceinline__ int eidx(const int* __restrict__ ei32, size_t pos, int is64, int M) {
    int v = ei32[is64 ? (pos << 1) : pos];
    if ((unsigned)v >= (unsigned)M) v = 0;
    return v;
}
__device__ __forceinline__ uint32_t s2u(const void* p) {
    uint32_t a;
    asm("{ .reg .u64 t; cvta.to.shared.u64 t, %1; cvt.u32.u64 %0, t; }" : "=r"(a) : "l"(p));
    return a;
}
__device__ __forceinline__ void ldsm_x4(uint32_t& r0, uint32_t& r1, uint32_t& r2, uint32_t& r3, uint32_t addr) {
    asm volatile("ldmatrix.sync.aligned.m8n8.x4.shared.b16 {%0,%1,%2,%3}, [%4];"
                 : "=r"(r0), "=r"(r1), "=r"(r2), "=r"(r3) : "r"(addr));
}
__device__ __forceinline__ void ldsm_x2(uint32_t& r0, uint32_t& r1, uint32_t addr) {
    asm volatile("ldmatrix.sync.aligned.m8n8.x2.shared.b16 {%0,%1}, [%2];"
                 : "=r"(r0), "=r"(r1) : "r"(addr));
}
__device__ __forceinline__ void mma_bf16(float* c, uint32_t a0, uint32_t a1, uint32_t a2, uint32_t a3,
                                         uint32_t b0, uint32_t b1) {
    asm volatile("mma.sync.aligned.m16n8k16.row.col.f32.bf16.bf16.f32 "
                 "{%0,%1,%2,%3}, {%4,%5,%6,%7}, {%8,%9}, {%0,%1,%2,%3};"
                 : "+f"(c[0]), "+f"(c[1]), "+f"(c[2]), "+f"(c[3])
                 : "r"(a0), "r"(a1), "r"(a2), "r"(a3), "r"(b0), "r"(b1));
}
__device__ __forceinline__ uint32_t pack_split(float a, float b, uint32_t& lo) {
    __nv_bfloat16 ha = __float2bfloat16(a), hb = __float2bfloat16(b);
    float ra = a - __bfloat162float(ha), rb = b - __bfloat162float(hb);
    __nv_bfloat16 la = __float2bfloat16(ra), lb = __float2bfloat16(rb);
    unsigned short uha = *(unsigned short*)&ha, uhb = *(unsigned short*)&hb;
    unsigned short ula = *(unsigned short*)&la, ulb = *(unsigned short*)&lb;
    lo = (uint32_t)ula | ((uint32_t)ulb << 16);
    return (uint32_t)uha | ((uint32_t)uhb << 16);
}

// ---------------- merged setup: style | bias2+detect | zdeg | wconv x6 ----------------
__device__ __forceinline__ void wconv_one(const float* __restrict__ W, int kdim, int ndim,
                                          int dstOff, int t) {
    int kh = kdim >> 1;
    int tot = ndim * kh;
    if (t >= tot) return;
    int n = t / kh, kp = t % kh;
    float a = W[(size_t)(2 * kp) * ndim + n];
    float b = W[(size_t)(2 * kp + 1) * ndim + n];
    uint32_t l, h = pack_split(a, b, l);
    uint32_t* ws = (uint32_t*)(g_scratch + OFF_WSTG) + dstOff;
    ws[(size_t)n * kh + kp] = h;
    ws[(size_t)tot + (size_t)n * kh + kp] = l;
}

__global__ void k_setup(const int* __restrict__ ei,
                        const float* __restrict__ t_emb, const float* __restrict__ fcW,
                        const float* __restrict__ fcb, const float* __restrict__ gatb,
                        const float* __restrict__ Wp, const float* __restrict__ bp,
                        const float* __restrict__ Wl, const float* __restrict__ Wr,
                        const float* __restrict__ We, const float* __restrict__ W1,
                        const float* __restrict__ W2, int E, int M) {
    int b = blockIdx.x, t = threadIdx.x;
    int ZB = (M + 255) >> 8;
    if (b == 0) {   // style (256 outputs)
        float s = fcb[t];
        for (int i = 0; i < 128; i++) s += t_emb[i] * fcW[i * 256 + t];
        g_scratch[OFF_STYLE + t] = s;
        return;
    }
    b -= 1;
    if (b == 0) {   // bias2 (128) + dtype detect
        if (t < 128) {
            float s = bp[t];
            for (int i = 0; i < 128; i++) s += gatb[i] * Wp[i * 128 + t];
            g_scratch[OFF_BIAS2 + t] = s;
        } else if (t == 128) {
            int z = 0;
#pragma unroll
            for (int i = 0; i < 16; i++) z |= ei[2 * i + 1];
            g_is64 = (z == 0) ? 1 : 0;
        }
        return;
    }
    b -= 1;
    if (b < ZB) {   // zero degree counters
        int i = b * 256 + t;
        if (i < M) csr_base()[E + M + 1 + i] = 0;
        return;
    }
    b -= ZB;
    if (b < 32) { wconv_one(Wl, 128, 128, WS_WL, b * 256 + t); return; }
    b -= 32;
    if (b < 32) { wconv_one(Wr, 128, 128, WS_WR, b * 256 + t); return; }
    b -= 32;
    if (b < 32) { wconv_one(We, 128, 128, WS_WE, b * 256 + t); return; }
    b -= 32;
    if (b < 32) { wconv_one(Wp, 128, 128, WS_WP, b * 256 + t); return; }
    b -= 32;
    if (b < 64) { wconv_one(W1, 128, 256, WS_W1, b * 256 + t); return; }
    b -= 64;
    if (b < 64) { wconv_one(W2, 256, 128, WS_W2, b * 256 + t); return; }
}

// ---------------- CSR build ----------------
__global__ void k_prep(const int* __restrict__ ei, int E, int M) {
    int e = blockIdx.x * 256 + threadIdx.x;
    if (e >= E) return;
    int d = eidx(ei, (size_t)E + e, g_is64, M);
    atomicAdd(&csr_base()[E + M + 1 + d], 1);
}
__global__ void __launch_bounds__(1024) k_scan(int E, int M) {
    __shared__ int ssum[1024];
    int* IA = csr_base();
    int* off = IA + E;
    int* cur = IA + E + M + 1;
    int t = threadIdx.x;
    int C = (M + 1023) >> 10;
    int lo = t * C, hi = lo + C; if (hi > M) hi = M; if (lo > M) lo = M;
    int s = 0;
    for (int i = lo; i < hi; i++) s += cur[i];
    ssum[t] = s;
    __syncthreads();
    for (int o = 1; o < 1024; o <<= 1) {
        int v = (t >= o) ? ssum[t - o] : 0;
        __syncthreads();
        ssum[t] += v;
        __syncthreads();
    }
    int pre = (t == 0) ? 0 : ssum[t - 1];
    for (int i = lo; i < hi; i++) {
        int d = cur[i];
        off[i] = pre;
        cur[i] = pre;
        pre += d;
    }
    if (t == 1023) off[M] = ssum[1023];
}
__global__ void k_fill(const int* __restrict__ ei, int E, int M) {
    int e = blockIdx.x * 256 + threadIdx.x;
    if (e >= E) return;
    int is64 = g_is64;
    int s = eidx(ei, (size_t)e, is64, M);
    int d = eidx(ei, (size_t)E + e, is64, M);
    int* IA = csr_base();
    int p = atomicAdd(&IA[E + M + 1 + d], 1);
    IA[p] = s;
}

// ---------------- AdaGN (warp per node, float4) -> packed bf16 hi/lo ----------------
__global__ void __launch_bounds__(256) k_adagn(const float* __restrict__ hs,
                                               const float* __restrict__ gnw,
                                               const float* __restrict__ gnb, int M) {
    int n = blockIdx.x * 8 + (threadIdx.x >> 5);
    if (n >= M) return;
    int l = threadIdx.x & 31;
    float4 v = ((const float4*)(hs + (size_t)n * 128))[l];
    float s = v.x + v.y + v.z + v.w;
    float q = v.x * v.x + v.y * v.y + v.z * v.z + v.w * v.w;
    s += __shfl_xor_sync(0xffffffffu, s, 1);
    q += __shfl_xor_sync(0xffffffffu, q, 1);
    s += __shfl_xor_sync(0xffffffffu, s, 2);
    q += __shfl_xor_sync(0xffffffffu, q, 2);
    float mean = s * (1.f / 16.f);
    float var  = q * (1.f / 16.f) - mean * mean;
    float rstd = rsqrtf(var + 1e-5f);
    int c = 4 * l;
    float4 w4 = *(const float4*)&gnw[c];
    float4 b4 = *(const float4*)&gnb[c];
    float4 g4 = *(const float4*)&g_scratch[OFF_STYLE + c];
    float4 e4 = *(const float4*)&g_scratch[OFF_STYLE + 128 + c];
    float h0 = ((v.x - mean) * rstd * w4.x + b4.x) * (1.f + g4.x) + e4.x;
    float h1 = ((v.y - mean) * rstd * w4.y + b4.y) * (1.f + g4.y) + e4.y;
    float h2 = ((v.z - mean) * rstd * w4.z + b4.z) * (1.f + g4.z) + e4.z;
    float h3 = ((v.w - mean) * rstd * w4.w + b4.w) * (1.f + g4.w) + e4.w;
    uint32_t l0, l1;
    uint32_t p0 = pack_split(h0, h1, l0);
    uint32_t p1 = pack_split(h2, h3, l1);
    uint32_t* st = (uint32_t*)(g_scratch + OFF_HMOD);
    st[(size_t)n * 64 + 2 * l]     = p0;
    st[(size_t)n * 64 + 2 * l + 1] = p1;
    st[(size_t)NN * 64 + (size_t)n * 64 + 2 * l]     = l0;
    st[(size_t)NN * 64 + (size_t)n * 64 + 2 * l + 1] = l1;
}

// ======================================================================
// HMMA bf16 3-term split GEMM core
// ======================================================================
constexpr int SLDA  = 136;
constexpr int TILEH = 128 * SLDA;
constexpr int AHI_H = 0;
constexpr int ALO_H = TILEH;
constexpr int BHI_H = 2 * TILEH;
constexpr int BLO_H = 3 * TILEH;
constexpr int SMEM_BYTES = 4 * TILEH * 2;

__device__ __forceinline__ void ld_tile(char* dsm, int half_base, const uint32_t* __restrict__ src,
                                        int ld32, int k32off, int rowBase, int rowMax, int tid) {
#pragma unroll
    for (int it = 0; it < 8; it++) {
        int idx = it * 256 + tid;
        int row = idx >> 4, c16 = idx & 15;
        int gr = rowBase + row;
        if (gr > rowMax) gr = rowMax;
        uint4 v = *(const uint4*)(src + (size_t)gr * ld32 + k32off + c16 * 4);
        *(uint4*)(dsm + 2 * (half_base + row * SLDA) + c16 * 16) = v;
    }
}

__device__ __forceinline__ void mma_chunk(uint32_t sb, int wm, int wn, int lane, float c[4][4][4]) {
    const int lrA = lane & 15, lcA = (lane >> 4) << 3;
    const int lrB = lane & 7,  lcB = ((lane >> 3) & 1) << 3;
#pragma unroll
    for (int ks = 0; ks < 8; ks++) {
        uint32_t ah[4][4], al[4][4];
#pragma unroll
        for (int mi = 0; mi < 4; mi++) {
            uint32_t addr = sb + 2u * (uint32_t)((wm * 64 + mi * 16 + lrA) * SLDA + ks * 16 + lcA);
            ldsm_x4(ah[mi][0], ah[mi][1], ah[mi][2], ah[mi][3], addr);
            ldsm_x4(al[mi][0], al[mi][1], al[mi][2], al[mi][3], addr + 2u * (uint32_t)ALO_H);
        }
#pragma unroll
        for (int ni = 0; ni < 4; ni++) {
            uint32_t baddr = sb + 2u * (uint32_t)(BHI_H + (wn * 32 + ni * 8 + lrB) * SLDA + ks * 16 + lcB);
            uint32_t bh0, bh1, bl0, bl1;
            ldsm_x2(bh0, bh1, baddr);
            ldsm_x2(bl0, bl1, baddr + 2u * (uint32_t)(BLO_H - BHI_H));
#pragma unroll
            for (int mi = 0; mi < 4; mi++) {
                mma_bf16(c[mi][ni], ah[mi][0], ah[mi][1], ah[mi][2], ah[mi][3], bh0, bh1);
                mma_bf16(c[mi][ni], al[mi][0], al[mi][1], al[mi][2], al[mi][3], bh0, bh1);
                mma_bf16(c[mi][ni], ah[mi][0], ah[mi][1], ah[mi][2], ah[mi][3], bl0, bl1);
            }
        }
    }
}

// generic GEMM: modes 0 plain fp32, 1 GELU->packed bf16, 2 fp32 + extra residual
__global__ void __launch_bounds__(256, 1) k_mma(
    const uint32_t* __restrict__ Ahi, const uint32_t* __restrict__ Alo, int lda32,
    const uint32_t* __restrict__ Bhi, const uint32_t* __restrict__ Blo, int ldb32,
    const float* __restrict__ bias, int mode,
    float* __restrict__ Cf, int ldc, const float* __restrict__ extra,
    uint32_t* __restrict__ Cohi, uint32_t* __restrict__ Colo, int ldco,
    int M, int K)
{
    extern __shared__ __align__(16) char dsm[];
    const int tid = threadIdx.x;
    const int w = tid >> 5, lane = tid & 31;
    const uint32_t sb = s2u(dsm);
    const int rowBase = blockIdx.x * 128;
    const int nBase = blockIdx.y * 128;
    const int wm = w & 1, wn = w >> 1;

    const uint32_t* bh = Bhi + (size_t)nBase * ldb32;
    const uint32_t* bl = Blo + (size_t)nBase * ldb32;

    float c[4][4][4];
#pragma unroll
    for (int i = 0; i < 4; i++)
#pragma unroll
        for (int j = 0; j < 4; j++)
#pragma unroll
            for (int q = 0; q < 4; q++) c[i][j][q] = 0.f;

    for (int kt = 0; kt < K; kt += 128) {
        int k32 = kt >> 1;
        ld_tile(dsm, AHI_H, Ahi, lda32, k32, rowBase, M - 1, tid);
        ld_tile(dsm, ALO_H, Alo, lda32, k32, rowBase, M - 1, tid);
        ld_tile(dsm, BHI_H, bh, ldb32, k32, 0, 127, tid);
        ld_tile(dsm, BLO_H, bl, ldb32, k32, 0, 127, tid);
        __syncthreads();
        mma_chunk(sb, wm, wn, lane, c);
        __syncthreads();
    }

    const int gq = lane >> 2;
    const int c2 = (lane & 3) * 2;
#pragma unroll
    for (int mi = 0; mi < 4; mi++) {
#pragma unroll
        for (int ni = 0; ni < 4; ni++) {
            int colg = nBase + wn * 32 + ni * 8 + c2;
            float2 bb = *(const float2*)&bias[colg];
#pragma unroll
            for (int half = 0; half < 2; half++) {
                int gr = rowBase + wm * 64 + mi * 16 + gq + half * 8;
                if (gr >= M) continue;
                float v0 = c[mi][ni][half * 2 + 0] + bb.x;
                float v1 = c[mi][ni][half * 2 + 1] + bb.y;
                if (mode == 0) {
                    *(float2*)&Cf[(size_t)gr * ldc + colg] = make_float2(v0, v1);
                } else if (mode == 1) {
                    uint32_t l, h = pack_split(geluf(v0), geluf(v1), l);
                    Cohi[(size_t)gr * ldco + (colg >> 1)] = h;
                    Colo[(size_t)gr * ldco + (colg >> 1)] = l;
                } else {
                    float2 r4 = *(const float2*)&extra[(size_t)gr * 128 + colg];
                    *(float2*)&Cf[(size_t)gr * ldc + colg] = make_float2(v0 + r4.x, v1 + r4.y);
                }
            }
        }
    }
}

// fused node-transform GEMM: A (HM bf16) loaded once, loop over Wl/Wr/We
__global__ void __launch_bounds__(256, 1) k_mma3(
    const uint32_t* __restrict__ Ahi, const uint32_t* __restrict__ Alo,
    const float* __restrict__ bl_, const float* __restrict__ br_,
    float* __restrict__ P, float* __restrict__ XR, int M)
{
    extern __shared__ __align__(16) char dsm[];
    const int tid = threadIdx.x;
    const int w = tid >> 5, lane = tid & 31;
    const uint32_t sb = s2u(dsm);
    const int rowBase = blockIdx.x * 128;
    const int wm = w & 1, wn = w >> 1;
    const uint32_t* ws = (const uint32_t*)(g_scratch + OFF_WSTG);
    const int wsoff[3] = {WS_WL, WS_WR, WS_WE};

    ld_tile(dsm, AHI_H, Ahi, 64, 0, rowBase, M - 1, tid);
    ld_tile(dsm, ALO_H, Alo, 64, 0, rowBase, M - 1, tid);
    ld_tile(dsm, BHI_H, ws + wsoff[0], 64, 0, 0, 127, tid);
    ld_tile(dsm, BLO_H, ws + wsoff[0] + 8192, 64, 0, 0, 127, tid);
    __syncthreads();

    const int gq = lane >> 2;
    const int c2 = (lane & 3) * 2;

#pragma unroll
    for (int t = 0; t < 3; t++) {
        float c[4][4][4];
#pragma unroll
        for (int i = 0; i < 4; i++)
#pragma unroll
            for (int j = 0; j < 4; j++)
#pragma unroll
                for (int q = 0; q < 4; q++) c[i][j][q] = 0.f;

        mma_chunk(sb, wm, wn, lane, c);

#pragma unroll
        for (int mi = 0; mi < 4; mi++) {
#pragma unroll
            for (int ni = 0; ni < 4; ni++) {
                int colg = wn * 32 + ni * 8 + c2;
                float2 bb = make_float2(0.f, 0.f);
                if (t == 0) bb = *(const float2*)&bl_[colg];
                else if (t == 1) bb = *(const float2*)&br_[colg];
#pragma unroll
                for (int half = 0; half < 2; half++) {
                    int gr = rowBase + wm * 64 + mi * 16 + gq + half * 8;
                    if (gr >= M) continue;
                    float v0 = c[mi][ni][half * 2 + 0] + bb.x;
                    float v1 = c[mi][ni][half * 2 + 1] + bb.y;
                    if (t == 0) {
                        *(float2*)&P[(size_t)gr * 384 + colg] = make_float2(v0, v1);
                    } else if (t == 1) {
                        *(float2*)&XR[(size_t)gr * 128 + colg] = make_float2(v0, v1);
                    } else {
                        float2 xl = *(const float2*)&P[(size_t)gr * 384 + colg];
                        float2 xr = *(const float2*)&XR[(size_t)gr * 128 + colg];
                        *(float2*)&P[(size_t)gr * 384 + 128 + colg] = make_float2(xl.x + v0, xl.y + v1);
                        *(float2*)&P[(size_t)gr * 384 + 256 + colg] = make_float2(xr.x - v0, xr.y - v1);
                    }
                }
            }
        }
        __syncthreads();
        if (t < 2) {
            ld_tile(dsm, BHI_H, ws + wsoff[t + 1], 64, 0, 0, 127, tid);
            ld_tile(dsm, BLO_H, ws + wsoff[t + 1] + 8192, 64, 0, 0, 127, tid);
            __syncthreads();
        }
    }
}

// ---------------- fused GAT attention: single-pass online softmax, unroll x2 ----------------
__global__ void __launch_bounds__(256) k_attn(const float* __restrict__ pos,
                                              const float* __restrict__ We,
                                              const float* __restrict__ att, int E, int M) {
    int n = blockIdx.x * 8 + (threadIdx.x >> 5);
    if (n >= M) return;
    int l = threadIdx.x & 31;
    const int* list = csr_base();
    const int* off = list + E;
    int off0 = off[n], off1 = off[n + 1];

    float2 pd = ((const float2*)pos)[n];
    float4 b4 = *(const float4*)(g_scratch + OFF_P + (size_t)n * 384 + 256 + 4 * l);
    float4 at = *(const float4*)(att + 4 * l);
    float4 c0 = *(const float4*)(We + 128 * 128 + 4 * l);
    float4 c1 = *(const float4*)(We + 129 * 128 + 4 * l);

    float mh = -1e30f, den = 0.f;
    float4 acc = make_float4(0.f, 0.f, 0.f, 0.f);

    int p = off0;
    for (; p + 1 < off1; p += 2) {
        int s0 = list[p];
        int s1 = list[p + 1];
        float2 ps0 = ((const float2*)pos)[s0];
        float2 ps1 = ((const float2*)pos)[s1];
        const float* r0 = g_scratch + OFF_P + (size_t)s0 * 384;
        const float* r1 = g_scratch + OFF_P + (size_t)s1 * 384;
        float4 a0 = *(const float4*)(r0 + 128 + 4 * l);
        float4 x0 = *(const float4*)(r0 + 4 * l);
        float4 a1 = *(const float4*)(r1 + 128 + 4 * l);
        float4 x1 = *(const float4*)(r1 + 4 * l);

        float rx0 = ps0.x - pd.x, ry0 = ps0.y - pd.y;
        float d0 = rx0 * rx0 + ry0 * ry0 + 1e-8f;
        float ox0 = -ry0 / d0, oy0 = rx0 / d0;
        float rx1 = ps1.x - pd.x, ry1 = ps1.y - pd.y;
        float d1 = rx1 * rx1 + ry1 * ry1 + 1e-8f;
        float ox1 = -ry1 / d1, oy1 = rx1 / d1;

        float t0x = a0.x + b4.x + ox0 * c0.x + oy0 * c1.x;
        float t0y = a0.y + b4.y + ox0 * c0.y + oy0 * c1.y;
        float t0z = a0.z + b4.z + ox0 * c0.z + oy0 * c1.z;
        float t0w = a0.w + b4.w + ox0 * c0.w + oy0 * c1.w;
        float t1x = a1.x + b4.x + ox1 * c0.x + oy1 * c1.x;
        float t1y = a1.y + b4.y + ox1 * c0.y + oy1 * c1.y;
        float t1z = a1.z + b4.z + ox1 * c0.z + oy1 * c1.z;
        float t1w = a1.w + b4.w + ox1 * c0.w + oy1 * c1.w;
        t0x = t0x > 0.f ? t0x : 0.2f * t0x;
        t0y = t0y > 0.f ? t0y : 0.2f * t0y;
        t0z = t0z > 0.f ? t0z : 0.2f * t0z;
        t0w = t0w > 0.f ? t0w : 0.2f * t0w;
        t1x = t1x > 0.f ? t1x : 0.2f * t1x;
        t1y = t1y > 0.f ? t1y : 0.2f * t1y;
        t1z = t1z > 0.f ? t1z : 0.2f * t1z;
        t1w = t1w > 0.f ? t1w : 0.2f * t1w;
        float lg0 = t0x * at.x + t0y * at.y + t0z * at.z + t0w * at.w;
        float lg1 = t1x * at.x + t1y * at.y + t1z * at.z + t1w * at.w;
        lg0 += __shfl_xor_sync(0xffffffffu, lg0, 4);
        lg1 += __shfl_xor_sync(0xffffffffu, lg1, 4);
        lg0 += __shfl_xor_sync(0xffffffffu, lg0, 2);
        lg1 += __shfl_xor_sync(0xffffffffu, lg1, 2);
        lg0 += __shfl_xor_sync(0xffffffffu, lg0, 1);
        lg1 += __shfl_xor_sync(0xffffffffu, lg1, 1);

        float mnew = fmaxf(mh, fmaxf(lg0, lg1));
        float scale = __expf(mh - mnew);
        float al0 = __expf(lg0 - mnew);
        float al1 = __expf(lg1 - mnew);
        den = den * scale + al0 + al1;
        acc.x = acc.x * scale + x0.x * al0 + x1.x * al1;
        acc.y = acc.y * scale + x0.y * al0 + x1.y * al1;
        acc.z = acc.z * scale + x0.z * al0 + x1.z * al1;
        acc.w = acc.w * scale + x0.w * al0 + x1.w * al1;
        mh = mnew;
    }
    if (p < off1) {
        int s = list[p];
        float2 ps = ((const float2*)pos)[s];
        const float* rowp = g_scratch + OFF_P + (size_t)s * 384;
        float4 a4 = *(const float4*)(rowp + 128 + 4 * l);
        float4 xl = *(const float4*)(rowp + 4 * l);
        float rx = ps.x - pd.x, ry = ps.y - pd.y;
        float dsq = rx * rx + ry * ry + 1e-8f;
        float ox = -ry / dsq, oy = rx / dsq;
        float xx = a4.x + b4.x + ox * c0.x + oy * c1.x;
        float xy = a4.y + b4.y + ox * c0.y + oy * c1.y;
        float xz = a4.z + b4.z + ox * c0.z + oy * c1.z;
        float xw = a4.w + b4.w + ox * c0.w + oy * c1.w;
        xx = xx > 0.f ? xx : 0.2f * xx;
        xy = xy > 0.f ? xy : 0.2f * xy;
        xz = xz > 0.f ? xz : 0.2f * xz;
        xw = xw > 0.f ? xw : 0.2f * xw;
        float lg = xx * at.x + xy * at.y + xz * at.z + xw * at.w;
        lg += __shfl_xor_sync(0xffffffffu, lg, 4);
        lg += __shfl_xor_sync(0xffffffffu, lg, 2);
        lg += __shfl_xor_sync(0xffffffffu, lg, 1);
        float mnew = fmaxf(mh, lg);
        float scale = __expf(mh - mnew);
        float al = __expf(lg - mnew);
        den = den * scale + al;
        acc.x = acc.x * scale + xl.x * al;
        acc.y = acc.y * scale + xl.y * al;
        acc.z = acc.z * scale + xl.z * al;
        acc.w = acc.w * scale + xl.w * al;
        mh = mnew;
    }

    float r = 1.f / (den + 1e-16f);
    acc.x *= r; acc.y *= r; acc.z *= r; acc.w *= r;

    uint32_t l0, l1;
    uint32_t h0 = pack_split(acc.x, acc.y, l0);
    uint32_t h1 = pack_split(acc.z, acc.w, l1);
    uint32_t* st = (uint32_t*)(g_scratch + OFF_HMOD);
    st[(size_t)n * 64 + 2 * l]     = h0;
    st[(size_t)n * 64 + 2 * l + 1] = h1;
    st[(size_t)NN * 64 + (size_t)n * 64 + 2 * l]     = l0;
    st[(size_t)NN * 64 + (size_t)n * 64 + 2 * l + 1] = l1;
}

// ---------------- LayerNorm -> packed bf16 hi/lo staging ----------------
__global__ void __launch_bounds__(256) k_ln(const float* __restrict__ lnw,
                                            const float* __restrict__ lnb, int M) {
    int n = blockIdx.x * 8 + (threadIdx.x >> 5);
    if (n >= M) return;
    int l = threadIdx.x & 31;
    float4 v = ((const float4*)(g_scratch + OFF_AGGR2 + (size_t)n * 128))[l];
    float s = v.x + v.y + v.z + v.w;
    float q = v.x * v.x + v.y * v.y + v.z * v.z + v.w * v.w;
#pragma unroll
    for (int o = 16; o; o >>= 1) {
        s += __shfl_xor_sync(0xffffffffu, s, o);
        q += __shfl_xor_sync(0xffffffffu, q, o);
    }
    float mean = s * (1.f / 128.f);
    float var  = q * (1.f / 128.f) - mean * mean;
    float rstd = rsqrtf(var + 1e-5f);
    float4 w = ((const float4*)lnw)[l];
    float4 b = ((const float4*)lnb)[l];
    float4 o4;
    o4.x = (v.x - mean) * rstd * w.x + b.x;
    o4.y = (v.y - mean) * rstd * w.y + b.y;
    o4.z = (v.z - mean) * rstd * w.z + b.z;
    o4.w = (v.w - mean) * rstd * w.w + b.w;
    uint32_t l0, l1;
    uint32_t h0 = pack_split(o4.x, o4.y, l0);
    uint32_t h1 = pack_split(o4.z, o4.w, l1);
    uint32_t* st = (uint32_t*)(g_scratch + OFF_HMOD);
    st[(size_t)n * 64 + 2 * l]     = h0;
    st[(size_t)n * 64 + 2 * l + 1] = h1;
    st[(size_t)NN * 64 + (size_t)n * 64 + 2 * l]     = l0;
    st[(size_t)NN * 64 + (size_t)n * 64 + 2 * l + 1] = l1;
}

// ---------------- launch ----------------
extern "C" void kernel_launch(void* const* d_in, const int* in_sizes, int n_in,
                              void* d_out, int out_size) {
    const float* h_target = (const float*)d_in[0];
    const float* h_source = (const float*)d_in[1];
    const int* ei      = (const int*)d_in[2];
    const float* pos   = (const float*)d_in[3];
    const float* t_emb = (const float*)d_in[4];
    const float* gn_w  = (const float*)d_in[5];
    const float* gn_b  = (const float*)d_in[6];
    const float* fcW   = (const float*)d_in[7];
    const float* fcb   = (const float*)d_in[8];
    const float* Wl    = (const float*)d_in[9];
    const float* bl    = (const float*)d_in[10];
    const float* Wr    = (const float*)d_in[11];
    const float* br    = (const float*)d_in[12];
    const float* We    = (const float*)d_in[13];
    const float* att   = (const float*)d_in[14];
    const float* gatb  = (const float*)d_in[15];
    const float* Wp    = (const float*)d_in[16];
    const float* bp    = (const float*)d_in[17];
    const float* lnw   = (const float*)d_in[18];
    const float* lnb   = (const float*)d_in[19];
    const float* W1    = (const float*)d_in[20];
    const float* b1    = (const float*)d_in[21];
    const float* W2    = (const float*)d_in[22];
    const float* b2    = (const float*)d_in[23];

    int M = in_sizes[0] / 128; if (M > NN) M = NN;
    int E = in_sizes[2] / 2;   if (E > EE) E = EE;

    float* sc = nullptr;
    cudaGetSymbolAddress((void**)&sc, g_scratch);
    float* P     = sc + OFF_P;
    float* AGGR2 = sc + OFF_AGGR2;
    float* BIAS2 = sc + OFF_BIAS2;
    uint32_t* HMB  = (uint32_t*)(sc + OFF_HMOD);
    uint32_t* Z1HI = (uint32_t*)(sc + OFF_P) + (size_t)NN * 128;
    uint32_t* Z1LO = Z1HI + (size_t)NN * 128;
    uint32_t* WS   = (uint32_t*)(sc + OFF_WSTG);

    cudaFuncSetAttribute(k_mma,  cudaFuncAttributeMaxDynamicSharedMemorySize, SMEM_BYTES);
    cudaFuncSetAttribute(k_mma3, cudaFuncAttributeMaxDynamicSharedMemorySize, SMEM_BYTES);

    dim3 blk(256);
    dim3 g1((M + 127) / 128, 1);
    dim3 g2((M + 127) / 128, 2);

    // merged setup: style | bias2+detect | zdeg | 6x wconv
    int ZB = (M + 255) / 256;
    int setupBlocks = 2 + ZB + 32 * 4 + 64 * 2;
    k_setup<<<setupBlocks, 256>>>(ei, t_emb, fcW, fcb, gatb, Wp, bp,
                                  Wl, Wr, We, W1, W2, E, M);
    // CSR build
    k_prep<<<(E + 255) / 256, 256>>>(ei, E, M);
    k_scan<<<1, 1024>>>(E, M);
    k_fill<<<(E + 255) / 256, 256>>>(ei, E, M);

    k_adagn<<<(M + 7) / 8, 256>>>(h_source, gn_w, gn_b, M);

    // fused node transforms: x_l->P, x_r->AGGR2(temp), combine->P+128/P+256
    k_mma3<<<g1, blk, SMEM_BYTES>>>(HMB, HMB + (size_t)NN * 64, bl, br, P, AGGR2, M);

    // fused GAT: single-pass online softmax (x2 unroll) -> HMOD (bf16 hi/lo)
    k_attn<<<(M + 7) / 8, 256>>>(pos, We, att, E, M);

    // post_gat: aggr(bf16)@Wp + bias2 -> AGGR2 fp32
    k_mma<<<g1, blk, SMEM_BYTES>>>(HMB, HMB + (size_t)NN * 64, 64,
                                   WS + WS_WP, WS + WS_WP + 8192, 64,
                                   BIAS2, 0, AGGR2, 128, nullptr, nullptr, nullptr, 0, M, 128);
    k_ln<<<(M + 7) / 8, 256>>>(lnw, lnb, M);
    // W1 + GELU -> z1 bf16
    k_mma<<<g2, blk, SMEM_BYTES>>>(HMB, HMB + (size_t)NN * 64, 64,
                                   WS + WS_W1, WS + WS_W1 + 16384, 64,
                                   b1, 1, nullptr, 0, nullptr, Z1HI, Z1LO, 128, M, 128);
    // W2 + residual -> d_out
    k_mma<<<g1, blk, SMEM_BYTES>>>(Z1HI, Z1LO, 128,
                                   WS + WS_W2, WS + WS_W2 + 16384, 128,
                                   b2, 2, (float*)d_out, 128, h_target, nullptr, nullptr, 0, M, 256);
}